// round 1
// baseline (speedup 1.0000x reference)
#include <cuda_runtime.h>

// Problem constants
#define B_   4
#define C_   256
#define N_   4096          // H*W = 64*64
#define NH_  4
#define HD_  64
#define NG_  8
#define CPG_ 32            // channels per group
#define EPS_ 1e-5f
#define SCALE_ 0.125f      // HD^-0.5

// Scratch (no allocations allowed; __device__ globals are the sanctioned path)
__device__ float g_hn  [(size_t)B_ * C_     * N_];   // 16 MB  groupnorm output
__device__ float g_qkv [(size_t)B_ * 3 * C_ * N_];   // 48 MB  qkv activations
__device__ float g_ao  [(size_t)B_ * C_     * N_];   // 16 MB  attention output (c-major)
__device__ float g_stats[B_ * NG_ * 2];              // mean, rstd per (b,g)

// ---------------------------------------------------------------------------
// GroupNorm statistics: one block per (b, g); reduce 32*4096 elements.
// ---------------------------------------------------------------------------
__global__ void gn_stats_k(const float* __restrict__ x) {
    int bg = blockIdx.x;                       // b*NG_ + g  (channels contiguous)
    const float4* base = (const float4*)(x + (size_t)bg * CPG_ * N_);
    int tid = threadIdx.x;
    float s = 0.f, s2 = 0.f;
    const int nv = CPG_ * N_ / 4;              // 32768 float4
    for (int i = tid; i < nv; i += 256) {
        float4 v = base[i];
        s  += v.x + v.y + v.z + v.w;
        s2 += v.x * v.x + v.y * v.y + v.z * v.z + v.w * v.w;
    }
    __shared__ float rs[256], rq[256];
    rs[tid] = s; rq[tid] = s2;
    __syncthreads();
    for (int o = 128; o > 0; o >>= 1) {
        if (tid < o) { rs[tid] += rs[tid + o]; rq[tid] += rq[tid + o]; }
        __syncthreads();
    }
    if (tid == 0) {
        const float invn = 1.f / (float)(CPG_ * N_);
        float mean = rs[0] * invn;
        float var  = rq[0] * invn - mean * mean;
        g_stats[bg * 2 + 0] = mean;
        g_stats[bg * 2 + 1] = rsqrtf(var + EPS_);
    }
}

// ---------------------------------------------------------------------------
// GroupNorm apply: hn = (x - mean) * rstd * gamma + beta (float4 elementwise)
// ---------------------------------------------------------------------------
__global__ void gn_apply_k(const float* __restrict__ x,
                           const float* __restrict__ gw,
                           const float* __restrict__ gb) {
    int i = blockIdx.x * 256 + threadIdx.x;    // float4 index
    size_t e = (size_t)i * 4;
    int c  = (int)((e >> 12) & (C_ - 1));      // (e / 4096) % 256
    int bg = (int)(e >> 17);                   // e / (4096*32) = b*8 + c/32
    float mean = g_stats[bg * 2 + 0];
    float rstd = g_stats[bg * 2 + 1];
    float ga = gw[c] * rstd;
    float be = gb[c] - mean * ga;
    float4 v = ((const float4*)x)[i];
    float4 o;
    o.x = v.x * ga + be;
    o.y = v.y * ga + be;
    o.z = v.z * ga + be;
    o.w = v.w * ga + be;
    ((float4*)g_hn)[i] = o;
}

// ---------------------------------------------------------------------------
// Batched SGEMM: Out[b][m][n] = sum_c W[m][c] * In[b][c][n] + bias[m] (+ res)
// Block tile 64x64, 256 threads, 4x4 microtile, k-slab 16. N_ columns fixed.
// ---------------------------------------------------------------------------
__global__ void sgemm_k(const float* __restrict__ W,
                        const float* __restrict__ In,
                        const float* __restrict__ bias,
                        const float* __restrict__ res,
                        float* __restrict__ Out,
                        int M, int K) {
    int b  = blockIdx.z;
    const float* Inb  = In + (size_t)b * K * N_;
    float*       Outb = Out + (size_t)b * M * N_;
    const float* resb = res ? res + (size_t)b * M * N_ : nullptr;
    int m0 = blockIdx.y * 64, n0 = blockIdx.x * 64;

    __shared__ float As[16][68];   // transposed: As[k][m]
    __shared__ float Bs[16][64];   // Bs[k][n]

    int tid = threadIdx.x;
    int ty = tid >> 4, tx = tid & 15;
    int ar = tid >> 2;             // 0..63  (m row for A load)
    int ac = (tid & 3) * 4;        // 0,4,8,12 (k cols)
    int bc = tid >> 4;             // 0..15  (k row for B load)
    int bn = (tid & 15) * 4;       // n cols

    float acc[4][4] = {};

    for (int k0 = 0; k0 < K; k0 += 16) {
        float4 av = *(const float4*)&W[(size_t)(m0 + ar) * K + k0 + ac];
        As[ac + 0][ar] = av.x;
        As[ac + 1][ar] = av.y;
        As[ac + 2][ar] = av.z;
        As[ac + 3][ar] = av.w;
        *(float4*)&Bs[bc][bn] = *(const float4*)&Inb[(size_t)(k0 + bc) * N_ + n0 + bn];
        __syncthreads();
#pragma unroll
        for (int kk = 0; kk < 16; kk++) {
            float4 a4 = *(const float4*)&As[kk][ty * 4];
            float4 b4 = *(const float4*)&Bs[kk][tx * 4];
            float a[4] = {a4.x, a4.y, a4.z, a4.w};
            float bb[4] = {b4.x, b4.y, b4.z, b4.w};
#pragma unroll
            for (int i = 0; i < 4; i++)
#pragma unroll
                for (int j = 0; j < 4; j++) acc[i][j] += a[i] * bb[j];
        }
        __syncthreads();
    }

#pragma unroll
    for (int i = 0; i < 4; i++) {
        int m = m0 + ty * 4 + i;
        float bi = bias[m];
        size_t off = (size_t)m * N_ + n0 + tx * 4;
        float4 o;
        o.x = acc[i][0] + bi;
        o.y = acc[i][1] + bi;
        o.z = acc[i][2] + bi;
        o.w = acc[i][3] + bi;
        if (resb) {
            float4 r = *(const float4*)&resb[off];
            o.x += r.x; o.y += r.y; o.z += r.z; o.w += r.w;
        }
        *(float4*)&Outb[off] = o;
    }
}

// ---------------------------------------------------------------------------
// Fused flash attention: grid (N/64 qtiles, NH, B), 256 threads.
// Q,K,V stored d-major (64 rows x 4096 cols) inside g_qkv.
// Per block: 64 queries; stream 64-key tiles with online softmax.
// ---------------------------------------------------------------------------
#define ATT_SMEM ((64*64*2 + 64*68*2) * 4)     // 67584 bytes

__global__ void attn_k() {
    int qt = blockIdx.x, h = blockIdx.y, b = blockIdx.z;
    const float* qb = g_qkv + ((size_t)b * 3 * C_ + 0 * C_ + h * HD_) * N_;
    const float* kb = g_qkv + ((size_t)b * 3 * C_ + 1 * C_ + h * HD_) * N_;
    const float* vb = g_qkv + ((size_t)b * 3 * C_ + 2 * C_ + h * HD_) * N_;

    extern __shared__ float sm[];
    float* Qs  = sm;                 // [64][64]  Qs[d][q]  (pre-scaled)
    float* Ks  = Qs + 64 * 64;       // [64][64]  Ks[d][m]
    float* VsT = Ks + 64 * 64;       // [64][68]  VsT[m][d]
    float* Ps  = VsT + 64 * 68;      // [64][68]  Ps[m][q]

    int tid = threadIdx.x;
    int ty = tid >> 4, tx = tid & 15;
    int q0 = qt * 64;
    int r0 = tid >> 4;               // 0..15 row base for tile loads
    int c4 = (tid & 15) * 4;         // col*4

    // Load Q tile once, pre-scaled by 1/sqrt(d)
#pragma unroll
    for (int r = 0; r < 4; r++) {
        int d = r0 + r * 16;
        float4 v = *(const float4*)&qb[(size_t)d * N_ + q0 + c4];
        v.x *= SCALE_; v.y *= SCALE_; v.z *= SCALE_; v.w *= SCALE_;
        *(float4*)&Qs[d * 64 + c4] = v;
    }

    float rmax[4], rsum[4], acc[4][4];
#pragma unroll
    for (int i = 0; i < 4; i++) {
        rmax[i] = -1e30f; rsum[i] = 0.f;
#pragma unroll
        for (int j = 0; j < 4; j++) acc[i][j] = 0.f;
    }

    for (int m0 = 0; m0 < N_; m0 += 64) {
        // Load K tile (d-major) and V tile transposed -> VsT[m][d]
#pragma unroll
        for (int r = 0; r < 4; r++) {
            int d = r0 + r * 16;
            *(float4*)&Ks[d * 64 + c4] = *(const float4*)&kb[(size_t)d * N_ + m0 + c4];
            float4 v = *(const float4*)&vb[(size_t)d * N_ + m0 + c4];
            VsT[(c4 + 0) * 68 + d] = v.x;
            VsT[(c4 + 1) * 68 + d] = v.y;
            VsT[(c4 + 2) * 68 + d] = v.z;
            VsT[(c4 + 3) * 68 + d] = v.w;
        }
        __syncthreads();

        // S = Q^T K  (inner dim d = 64), thread owns S[4q][4m]
        float s[4][4] = {};
#pragma unroll 16
        for (int kk = 0; kk < 64; kk++) {
            float4 a4 = *(const float4*)&Qs[kk * 64 + ty * 4];
            float4 b4 = *(const float4*)&Ks[kk * 64 + tx * 4];
            float a[4] = {a4.x, a4.y, a4.z, a4.w};
            float bb[4] = {b4.x, b4.y, b4.z, b4.w};
#pragma unroll
            for (int i = 0; i < 4; i++)
#pragma unroll
                for (int j = 0; j < 4; j++) s[i][j] += a[i] * bb[j];
        }

        // Online softmax per query row (16 lanes share a row -> half-warp shfl)
#pragma unroll
        for (int i = 0; i < 4; i++) {
            float tm = fmaxf(fmaxf(s[i][0], s[i][1]), fmaxf(s[i][2], s[i][3]));
#pragma unroll
            for (int o = 8; o > 0; o >>= 1)
                tm = fmaxf(tm, __shfl_xor_sync(0xffffffffu, tm, o));
            float nm = fmaxf(rmax[i], tm);
            float corr = __expf(rmax[i] - nm);
            rmax[i] = nm;
            rsum[i] *= corr;
#pragma unroll
            for (int j = 0; j < 4; j++) acc[i][j] *= corr;
            float p0 = __expf(s[i][0] - nm);
            float p1 = __expf(s[i][1] - nm);
            float p2 = __expf(s[i][2] - nm);
            float p3 = __expf(s[i][3] - nm);
            float ls = p0 + p1 + p2 + p3;
#pragma unroll
            for (int o = 8; o > 0; o >>= 1)
                ls += __shfl_xor_sync(0xffffffffu, ls, o);
            rsum[i] += ls;
            Ps[(tx * 4 + 0) * 68 + ty * 4 + i] = p0;
            Ps[(tx * 4 + 1) * 68 + ty * 4 + i] = p1;
            Ps[(tx * 4 + 2) * 68 + ty * 4 + i] = p2;
            Ps[(tx * 4 + 3) * 68 + ty * 4 + i] = p3;
        }
        __syncthreads();

        // O += P @ V^T : thread owns O[4q][4d], inner dim m = 64
#pragma unroll 16
        for (int m = 0; m < 64; m++) {
            float4 a4 = *(const float4*)&Ps[m * 68 + ty * 4];
            float4 b4 = *(const float4*)&VsT[m * 68 + tx * 4];
            float a[4] = {a4.x, a4.y, a4.z, a4.w};
            float bb[4] = {b4.x, b4.y, b4.z, b4.w};
#pragma unroll
            for (int i = 0; i < 4; i++)
#pragma unroll
                for (int j = 0; j < 4; j++) acc[i][j] += a[i] * bb[j];
        }
        __syncthreads();   // protect Ks/VsT/Ps before next tile's loads
    }

    // Epilogue: normalize and write c-major for the proj GEMM
    float* aob = g_ao + ((size_t)b * C_ + h * HD_) * N_;
#pragma unroll
    for (int i = 0; i < 4; i++) {
        float inv = 1.f / rsum[i];
#pragma unroll
        for (int j = 0; j < 4; j++) {
            aob[(size_t)(tx * 4 + j) * N_ + q0 + ty * 4 + i] = acc[i][j] * inv;
        }
    }
}

// ---------------------------------------------------------------------------
// Launch sequence (graph-capturable: kernels only + pure query APIs)
// ---------------------------------------------------------------------------
extern "C" void kernel_launch(void* const* d_in, const int* in_sizes, int n_in,
                              void* d_out, int out_size) {
    const float* x    = (const float*)d_in[0];
    const float* gw   = (const float*)d_in[1];
    const float* gb   = (const float*)d_in[2];
    const float* qkvw = (const float*)d_in[3];
    const float* qkvb = (const float*)d_in[4];
    const float* pw   = (const float*)d_in[5];
    const float* pb   = (const float*)d_in[6];
    float* out = (float*)d_out;

    float *hn, *qkv, *ao;
    cudaGetSymbolAddress((void**)&hn,  g_hn);
    cudaGetSymbolAddress((void**)&qkv, g_qkv);
    cudaGetSymbolAddress((void**)&ao,  g_ao);

    // 1) GroupNorm stats
    gn_stats_k<<<B_ * NG_, 256>>>(x);
    // 2) GroupNorm apply
    gn_apply_k<<<(B_ * C_ * N_ / 4) / 256, 256>>>(x, gw, gb);
    // 3) QKV GEMM: (768 x 256) @ hn_b(256 x 4096) per batch
    {
        dim3 g(N_ / 64, (3 * C_) / 64, B_);
        sgemm_k<<<g, 256>>>(qkvw, hn, qkvb, nullptr, qkv, 3 * C_, C_);
    }
    // 4) Fused flash attention
    cudaFuncSetAttribute(attn_k, cudaFuncAttributeMaxDynamicSharedMemorySize, ATT_SMEM);
    {
        dim3 g(N_ / 64, NH_, B_);
        attn_k<<<g, 256, ATT_SMEM>>>();
    }
    // 5) proj GEMM + bias + residual -> d_out
    {
        dim3 g(N_ / 64, C_ / 64, B_);
        sgemm_k<<<g, 256>>>(pw, ao, pb, x, out, C_, C_);
    }
}

// round 2
// speedup vs baseline: 2.9347x; 2.9347x over previous
#include <cuda_runtime.h>
#include <cstdint>

// Problem constants
#define B_   4
#define C_   256
#define N_   4096          // H*W = 64*64
#define NH_  4
#define HD_  64
#define NG_  8
#define CPG_ 32            // channels per group
#define EPS_ 1e-5f
#define SCALE_ 0.125f      // HD^-0.5
#define LOG2E_ 1.4426950408889634f

// Scratch (no allocations allowed; __device__ globals are the sanctioned path)
__device__ float g_hn  [(size_t)B_ * C_     * N_];   // 16 MB  groupnorm output
__device__ float g_qkv [(size_t)B_ * 3 * C_ * N_];   // 48 MB  qkv activations
__device__ float g_ao  [(size_t)B_ * C_     * N_];   // 16 MB  attention output (c-major)
__device__ float g_stats[B_ * NG_ * 2];              // mean, rstd per (b,g)

// ---------------------------------------------------------------------------
// tf32 helpers
// ---------------------------------------------------------------------------
__device__ __forceinline__ uint32_t f2tf(float f) {
    uint32_t u;
    asm("cvt.rna.tf32.f32 %0, %1;" : "=r"(u) : "f"(f));
    return u;
}
__device__ __forceinline__ float ex2f(float x) {
    float y;
    asm("ex2.approx.ftz.f32 %0, %1;" : "=f"(y) : "f"(x));
    return y;
}
__device__ __forceinline__ void mma_tf32(float* d, const uint32_t* a, const uint32_t* b) {
    asm("mma.sync.aligned.m16n8k8.row.col.f32.tf32.tf32.f32 "
        "{%0,%1,%2,%3}, {%4,%5,%6,%7}, {%8,%9}, {%0,%1,%2,%3};"
        : "+f"(d[0]), "+f"(d[1]), "+f"(d[2]), "+f"(d[3])
        : "r"(a[0]), "r"(a[1]), "r"(a[2]), "r"(a[3]), "r"(b[0]), "r"(b[1]));
}

// ---------------------------------------------------------------------------
// GroupNorm statistics: one block per (b, g); reduce 32*4096 elements.
// ---------------------------------------------------------------------------
__global__ void gn_stats_k(const float* __restrict__ x) {
    int bg = blockIdx.x;
    const float4* base = (const float4*)(x + (size_t)bg * CPG_ * N_);
    int tid = threadIdx.x;
    float s = 0.f, s2 = 0.f;
    const int nv = CPG_ * N_ / 4;
    for (int i = tid; i < nv; i += 256) {
        float4 v = base[i];
        s  += v.x + v.y + v.z + v.w;
        s2 += v.x * v.x + v.y * v.y + v.z * v.z + v.w * v.w;
    }
    __shared__ float rs[256], rq[256];
    rs[tid] = s; rq[tid] = s2;
    __syncthreads();
    for (int o = 128; o > 0; o >>= 1) {
        if (tid < o) { rs[tid] += rs[tid + o]; rq[tid] += rq[tid + o]; }
        __syncthreads();
    }
    if (tid == 0) {
        const float invn = 1.f / (float)(CPG_ * N_);
        float mean = rs[0] * invn;
        float var  = rq[0] * invn - mean * mean;
        g_stats[bg * 2 + 0] = mean;
        g_stats[bg * 2 + 1] = rsqrtf(var + EPS_);
    }
}

// ---------------------------------------------------------------------------
// GroupNorm apply
// ---------------------------------------------------------------------------
__global__ void gn_apply_k(const float* __restrict__ x,
                           const float* __restrict__ gw,
                           const float* __restrict__ gb) {
    int i = blockIdx.x * 256 + threadIdx.x;
    size_t e = (size_t)i * 4;
    int c  = (int)((e >> 12) & (C_ - 1));
    int bg = (int)(e >> 17);
    float mean = g_stats[bg * 2 + 0];
    float rstd = g_stats[bg * 2 + 1];
    float ga = gw[c] * rstd;
    float be = gb[c] - mean * ga;
    float4 v = ((const float4*)x)[i];
    float4 o;
    o.x = v.x * ga + be;
    o.y = v.y * ga + be;
    o.z = v.z * ga + be;
    o.w = v.w * ga + be;
    ((float4*)g_hn)[i] = o;
}

// ---------------------------------------------------------------------------
// Batched SGEMM (unchanged from R1): Out = W @ In + bias (+ res)
// ---------------------------------------------------------------------------
__global__ void sgemm_k(const float* __restrict__ W,
                        const float* __restrict__ In,
                        const float* __restrict__ bias,
                        const float* __restrict__ res,
                        float* __restrict__ Out,
                        int M, int K) {
    int b  = blockIdx.z;
    const float* Inb  = In + (size_t)b * K * N_;
    float*       Outb = Out + (size_t)b * M * N_;
    const float* resb = res ? res + (size_t)b * M * N_ : nullptr;
    int m0 = blockIdx.y * 64, n0 = blockIdx.x * 64;

    __shared__ float As[16][68];
    __shared__ float Bs[16][64];

    int tid = threadIdx.x;
    int ty = tid >> 4, tx = tid & 15;
    int ar = tid >> 2;
    int ac = (tid & 3) * 4;
    int bc = tid >> 4;
    int bn = (tid & 15) * 4;

    float acc[4][4] = {};

    for (int k0 = 0; k0 < K; k0 += 16) {
        float4 av = *(const float4*)&W[(size_t)(m0 + ar) * K + k0 + ac];
        As[ac + 0][ar] = av.x;
        As[ac + 1][ar] = av.y;
        As[ac + 2][ar] = av.z;
        As[ac + 3][ar] = av.w;
        *(float4*)&Bs[bc][bn] = *(const float4*)&Inb[(size_t)(k0 + bc) * N_ + n0 + bn];
        __syncthreads();
#pragma unroll
        for (int kk = 0; kk < 16; kk++) {
            float4 a4 = *(const float4*)&As[kk][ty * 4];
            float4 b4 = *(const float4*)&Bs[kk][tx * 4];
            float a[4] = {a4.x, a4.y, a4.z, a4.w};
            float bb[4] = {b4.x, b4.y, b4.z, b4.w};
#pragma unroll
            for (int i = 0; i < 4; i++)
#pragma unroll
                for (int j = 0; j < 4; j++) acc[i][j] += a[i] * bb[j];
        }
        __syncthreads();
    }

#pragma unroll
    for (int i = 0; i < 4; i++) {
        int m = m0 + ty * 4 + i;
        float bi = bias[m];
        size_t off = (size_t)m * N_ + n0 + tx * 4;
        float4 o;
        o.x = acc[i][0] + bi;
        o.y = acc[i][1] + bi;
        o.z = acc[i][2] + bi;
        o.w = acc[i][3] + bi;
        if (resb) {
            float4 r = *(const float4*)&resb[off];
            o.x += r.x; o.y += r.y; o.z += r.z; o.w += r.w;
        }
        *(float4*)&Outb[off] = o;
    }
}

// ---------------------------------------------------------------------------
// Flash attention with tf32 tensor-core MMA.
// Grid (N/64, NH, B), 128 threads (4 warps). Warp w owns q rows [16w,16w+16).
// Q pre-scaled by SCALE*log2e, register-resident as m16n8k8 A fragments.
// K tile d-major in smem (stride 72), V tile d-major (stride 68): both give
// conflict-free B-fragment gathers. P staged per-warp in smem (stride 68).
// ---------------------------------------------------------------------------
#define KS_STR 72
#define VS_STR 68
#define PS_STR 68
#define ATT_SMEM ((64 * KS_STR + 64 * VS_STR + 4 * 16 * PS_STR) * 4)  // 53248 B

__global__ __launch_bounds__(128) void attn_k() {
    int qt = blockIdx.x, h = blockIdx.y, b = blockIdx.z;
    const float* qb = g_qkv + ((size_t)b * 3 * C_ + h * HD_) * N_;
    const float* kb = qb + (size_t)C_ * N_;
    const float* vb = qb + (size_t)2 * C_ * N_;

    extern __shared__ float sm[];
    uint32_t* Ks = (uint32_t*)sm;                  // [64][72] d-major tf32
    uint32_t* Vs = Ks + 64 * KS_STR;               // [64][68] d-major tf32
    uint32_t* Ps = Vs + 64 * VS_STR;               // 4 x [16][68] per-warp tf32

    int tid = threadIdx.x, w = tid >> 5, lane = tid & 31;
    int g = lane >> 2, m = lane & 3;
    uint32_t* Pw = Ps + w * 16 * PS_STR;
    int q0 = qt * 64;
    int ty = tid >> 4, tx = tid & 15;              // tile-loader layout

    // Q A-fragments, scaled so softmax works in log2 domain
    const float qs = SCALE_ * LOG2E_;
    uint32_t Af[8][4];
    int qlo = q0 + w * 16 + g, qhi = qlo + 8;
#pragma unroll
    for (int t = 0; t < 8; t++) {
        int d0 = t * 8 + m;
        Af[t][0] = f2tf(qb[(size_t)d0 * N_ + qlo] * qs);
        Af[t][1] = f2tf(qb[(size_t)d0 * N_ + qhi] * qs);
        Af[t][2] = f2tf(qb[(size_t)(d0 + 4) * N_ + qlo] * qs);
        Af[t][3] = f2tf(qb[(size_t)(d0 + 4) * N_ + qhi] * qs);
    }

    float O[8][4];
#pragma unroll
    for (int j = 0; j < 8; j++)
#pragma unroll
        for (int i = 0; i < 4; i++) O[j][i] = 0.f;
    float mlo = -1e30f, mhi = -1e30f, slo = 0.f, shi = 0.f;

    for (int k0t = 0; k0t < N_; k0t += 64) {
        __syncthreads();   // previous tile fully consumed
        // Load K,V tiles d-major, converting to tf32
#pragma unroll
        for (int r = 0; r < 8; r++) {
            int d = ty + r * 8;
            float4 kv = *(const float4*)&kb[(size_t)d * N_ + k0t + tx * 4];
            float4 vv = *(const float4*)&vb[(size_t)d * N_ + k0t + tx * 4];
            uint4 ku; ku.x = f2tf(kv.x); ku.y = f2tf(kv.y); ku.z = f2tf(kv.z); ku.w = f2tf(kv.w);
            uint4 vu; vu.x = f2tf(vv.x); vu.y = f2tf(vv.y); vu.z = f2tf(vv.z); vu.w = f2tf(vv.w);
            *(uint4*)&Ks[d * KS_STR + tx * 4] = ku;
            *(uint4*)&Vs[d * VS_STR + tx * 4] = vu;
        }
        __syncthreads();

        // S = Q K^T  (warp: 16q x 64k)
        float S[8][4];
#pragma unroll
        for (int j = 0; j < 8; j++) {
            S[j][0] = S[j][1] = S[j][2] = S[j][3] = 0.f;
#pragma unroll
            for (int t = 0; t < 8; t++) {
                uint32_t bf[2];
                bf[0] = Ks[(t * 8 + m) * KS_STR + j * 8 + g];
                bf[1] = Ks[(t * 8 + m + 4) * KS_STR + j * 8 + g];
                mma_tf32(S[j], Af[t], bf);
            }
        }

        // Online softmax (log2 domain). Rows: lo = qlo (c0,c1), hi = qhi (c2,c3)
        float tlo = -1e30f, thi = -1e30f;
#pragma unroll
        for (int j = 0; j < 8; j++) {
            tlo = fmaxf(tlo, fmaxf(S[j][0], S[j][1]));
            thi = fmaxf(thi, fmaxf(S[j][2], S[j][3]));
        }
#pragma unroll
        for (int o = 1; o <= 2; o <<= 1) {
            tlo = fmaxf(tlo, __shfl_xor_sync(0xffffffffu, tlo, o));
            thi = fmaxf(thi, __shfl_xor_sync(0xffffffffu, thi, o));
        }
        float nlo = fmaxf(mlo, tlo), nhi = fmaxf(mhi, thi);
        float clo = ex2f(mlo - nlo), chi = ex2f(mhi - nhi);
        mlo = nlo; mhi = nhi;
        float ssl = 0.f, ssh = 0.f;
#pragma unroll
        for (int j = 0; j < 8; j++) {
            float p0 = ex2f(S[j][0] - nlo);
            float p1 = ex2f(S[j][1] - nlo);
            float p2 = ex2f(S[j][2] - nhi);
            float p3 = ex2f(S[j][3] - nhi);
            ssl += p0 + p1; ssh += p2 + p3;
            O[j][0] *= clo; O[j][1] *= clo; O[j][2] *= chi; O[j][3] *= chi;
            uint2 lo2; lo2.x = f2tf(p0); lo2.y = f2tf(p1);
            uint2 hi2; hi2.x = f2tf(p2); hi2.y = f2tf(p3);
            *(uint2*)&Pw[g * PS_STR + j * 8 + 2 * m]       = lo2;
            *(uint2*)&Pw[(g + 8) * PS_STR + j * 8 + 2 * m] = hi2;
        }
#pragma unroll
        for (int o = 1; o <= 2; o <<= 1) {
            ssl += __shfl_xor_sync(0xffffffffu, ssl, o);
            ssh += __shfl_xor_sync(0xffffffffu, ssh, o);
        }
        slo = slo * clo + ssl;
        shi = shi * chi + ssh;
        __syncwarp();

        // O += P @ V  (warp: 16q x 64d)
#pragma unroll
        for (int t = 0; t < 8; t++) {
            uint32_t Ap[4];
            Ap[0] = Pw[g * PS_STR + t * 8 + m];
            Ap[1] = Pw[(g + 8) * PS_STR + t * 8 + m];
            Ap[2] = Pw[g * PS_STR + t * 8 + m + 4];
            Ap[3] = Pw[(g + 8) * PS_STR + t * 8 + m + 4];
#pragma unroll
            for (int j = 0; j < 8; j++) {
                uint32_t bf[2];
                bf[0] = Vs[(j * 8 + g) * VS_STR + t * 8 + m];
                bf[1] = Vs[(j * 8 + g) * VS_STR + t * 8 + m + 4];
                mma_tf32(O[j], Ap, bf);
            }
        }
        __syncwarp();   // Pw reads done before next tile's stores
    }

    // Epilogue: normalize and write c-major for the proj GEMM
    float* aob = g_ao + ((size_t)b * C_ + h * HD_) * N_;
    float ilo = 1.f / slo, ihi = 1.f / shi;
#pragma unroll
    for (int j = 0; j < 8; j++) {
        int d = j * 8 + 2 * m;
        aob[(size_t)d * N_ + qlo]       = O[j][0] * ilo;
        aob[(size_t)(d + 1) * N_ + qlo] = O[j][1] * ilo;
        aob[(size_t)d * N_ + qhi]       = O[j][2] * ihi;
        aob[(size_t)(d + 1) * N_ + qhi] = O[j][3] * ihi;
    }
}

// ---------------------------------------------------------------------------
// Launch sequence
// ---------------------------------------------------------------------------
extern "C" void kernel_launch(void* const* d_in, const int* in_sizes, int n_in,
                              void* d_out, int out_size) {
    const float* x    = (const float*)d_in[0];
    const float* gw   = (const float*)d_in[1];
    const float* gb   = (const float*)d_in[2];
    const float* qkvw = (const float*)d_in[3];
    const float* qkvb = (const float*)d_in[4];
    const float* pw   = (const float*)d_in[5];
    const float* pb   = (const float*)d_in[6];
    float* out = (float*)d_out;

    float *hn, *qkv, *ao;
    cudaGetSymbolAddress((void**)&hn,  g_hn);
    cudaGetSymbolAddress((void**)&qkv, g_qkv);
    cudaGetSymbolAddress((void**)&ao,  g_ao);

    gn_stats_k<<<B_ * NG_, 256>>>(x);
    gn_apply_k<<<(B_ * C_ * N_ / 4) / 256, 256>>>(x, gw, gb);
    {
        dim3 g(N_ / 64, (3 * C_) / 64, B_);
        sgemm_k<<<g, 256>>>(qkvw, hn, qkvb, nullptr, qkv, 3 * C_, C_);
    }
    cudaFuncSetAttribute(attn_k, cudaFuncAttributeMaxDynamicSharedMemorySize, ATT_SMEM);
    {
        dim3 g(N_ / 64, NH_, B_);
        attn_k<<<g, 128, ATT_SMEM>>>();
    }
    {
        dim3 g(N_ / 64, C_ / 64, B_);
        sgemm_k<<<g, 256>>>(pw, ao, pb, x, out, C_, C_);
    }
}

// round 3
// speedup vs baseline: 3.9698x; 1.3527x over previous
#include <cuda_runtime.h>
#include <cstdint>

// Problem constants
#define B_   4
#define C_   256
#define N_   4096          // H*W = 64*64
#define NH_  4
#define HD_  64
#define NG_  8
#define CPG_ 32            // channels per group
#define EPS_ 1e-5f
#define SCALE_ 0.125f      // HD^-0.5
#define LOG2E_ 1.4426950408889634f

// Scratch
__device__ float g_hn  [(size_t)B_ * C_     * N_];
__device__ float g_qkv [(size_t)B_ * 3 * C_ * N_];
__device__ float g_ao  [(size_t)B_ * C_     * N_];
__device__ float g_stats[B_ * NG_ * 2];

// ---------------------------------------------------------------------------
// helpers
// ---------------------------------------------------------------------------
__device__ __forceinline__ uint32_t f2tf(float f) {
    uint32_t u;
    asm("cvt.rna.tf32.f32 %0, %1;" : "=r"(u) : "f"(f));
    return u;
}
__device__ __forceinline__ float ex2f(float x) {
    float y;
    asm("ex2.approx.ftz.f32 %0, %1;" : "=f"(y) : "f"(x));
    return y;
}
// pack {lo: a, hi: b} as bf16x2
__device__ __forceinline__ uint32_t bf16x2(float a, float b) {
    uint32_t r;
    asm("cvt.rn.bf16x2.f32 %0, %1, %2;" : "=r"(r) : "f"(b), "f"(a));
    return r;
}
__device__ __forceinline__ void mma_tf32(float* d, const uint32_t* a, const uint32_t* b) {
    asm("mma.sync.aligned.m16n8k8.row.col.f32.tf32.tf32.f32 "
        "{%0,%1,%2,%3}, {%4,%5,%6,%7}, {%8,%9}, {%0,%1,%2,%3};"
        : "+f"(d[0]), "+f"(d[1]), "+f"(d[2]), "+f"(d[3])
        : "r"(a[0]), "r"(a[1]), "r"(a[2]), "r"(a[3]), "r"(b[0]), "r"(b[1]));
}
__device__ __forceinline__ void mma_bf16(float* d, const uint32_t* a, const uint32_t* b) {
    asm("mma.sync.aligned.m16n8k16.row.col.f32.bf16.bf16.f32 "
        "{%0,%1,%2,%3}, {%4,%5,%6,%7}, {%8,%9}, {%0,%1,%2,%3};"
        : "+f"(d[0]), "+f"(d[1]), "+f"(d[2]), "+f"(d[3])
        : "r"(a[0]), "r"(a[1]), "r"(a[2]), "r"(a[3]), "r"(b[0]), "r"(b[1]));
}

// ---------------------------------------------------------------------------
// GroupNorm statistics
// ---------------------------------------------------------------------------
__global__ void gn_stats_k(const float* __restrict__ x) {
    int bg = blockIdx.x;
    const float4* base = (const float4*)(x + (size_t)bg * CPG_ * N_);
    int tid = threadIdx.x;
    float s = 0.f, s2 = 0.f;
    const int nv = CPG_ * N_ / 4;
    for (int i = tid; i < nv; i += 256) {
        float4 v = base[i];
        s  += v.x + v.y + v.z + v.w;
        s2 += v.x * v.x + v.y * v.y + v.z * v.z + v.w * v.w;
    }
    __shared__ float rs[256], rq[256];
    rs[tid] = s; rq[tid] = s2;
    __syncthreads();
    for (int o = 128; o > 0; o >>= 1) {
        if (tid < o) { rs[tid] += rs[tid + o]; rq[tid] += rq[tid + o]; }
        __syncthreads();
    }
    if (tid == 0) {
        const float invn = 1.f / (float)(CPG_ * N_);
        float mean = rs[0] * invn;
        float var  = rq[0] * invn - mean * mean;
        g_stats[bg * 2 + 0] = mean;
        g_stats[bg * 2 + 1] = rsqrtf(var + EPS_);
    }
}

// ---------------------------------------------------------------------------
// GroupNorm apply
// ---------------------------------------------------------------------------
__global__ void gn_apply_k(const float* __restrict__ x,
                           const float* __restrict__ gw,
                           const float* __restrict__ gb) {
    int i = blockIdx.x * 256 + threadIdx.x;
    size_t e = (size_t)i * 4;
    int c  = (int)((e >> 12) & (C_ - 1));
    int bg = (int)(e >> 17);
    float mean = g_stats[bg * 2 + 0];
    float rstd = g_stats[bg * 2 + 1];
    float ga = gw[c] * rstd;
    float be = gb[c] - mean * ga;
    float4 v = ((const float4*)x)[i];
    float4 o;
    o.x = v.x * ga + be;
    o.y = v.y * ga + be;
    o.z = v.z * ga + be;
    o.w = v.w * ga + be;
    ((float4*)g_hn)[i] = o;
}

// ---------------------------------------------------------------------------
// tf32 tensor-core GEMM: Out[b] = W[M,K] @ In[b][K,N_] + bias (+ res)
// CTA 64m x 64n, 4 warps, warp = 16m x 64n, k-slab 32 (4 x k8 mma chunks).
// Bs stride 72 -> conflict-free B-fragment gathers.
// ---------------------------------------------------------------------------
__global__ __launch_bounds__(128) void sgemm_tc(const float* __restrict__ W,
                                                const float* __restrict__ In,
                                                const float* __restrict__ bias,
                                                const float* __restrict__ res,
                                                float* __restrict__ Out,
                                                int M, int K) {
    int b  = blockIdx.z;
    const float* Inb  = In + (size_t)b * K * N_;
    float*       Outb = Out + (size_t)b * M * N_;
    const float* resb = res ? res + (size_t)b * M * N_ : nullptr;
    int m0 = blockIdx.y * 64, n0 = blockIdx.x * 64;

    __shared__ uint32_t Bs[32 * 72];

    int tid = threadIdx.x, w = tid >> 5, lane = tid & 31;
    int g = lane >> 2, m = lane & 3;
    int ty = tid >> 4, tx = tid & 15;
    int r_lo = m0 + w * 16 + g, r_hi = r_lo + 8;

    float acc[8][4];
#pragma unroll
    for (int j = 0; j < 8; j++)
#pragma unroll
        for (int i = 0; i < 4; i++) acc[j][i] = 0.f;

    for (int k0 = 0; k0 < K; k0 += 32) {
        __syncthreads();
#pragma unroll
        for (int r = 0; r < 4; r++) {
            int krow = ty + r * 8;
            float4 v = *(const float4*)&Inb[(size_t)(k0 + krow) * N_ + n0 + tx * 4];
            uint4 u; u.x = f2tf(v.x); u.y = f2tf(v.y); u.z = f2tf(v.z); u.w = f2tf(v.w);
            *(uint4*)&Bs[krow * 72 + tx * 4] = u;
        }
        __syncthreads();
#pragma unroll
        for (int t = 0; t < 4; t++) {
            uint32_t a[4];
            a[0] = f2tf(W[(size_t)r_lo * K + k0 + t * 8 + m]);
            a[1] = f2tf(W[(size_t)r_hi * K + k0 + t * 8 + m]);
            a[2] = f2tf(W[(size_t)r_lo * K + k0 + t * 8 + m + 4]);
            a[3] = f2tf(W[(size_t)r_hi * K + k0 + t * 8 + m + 4]);
#pragma unroll
            for (int j = 0; j < 8; j++) {
                uint32_t bb[2];
                bb[0] = Bs[(t * 8 + m) * 72 + j * 8 + g];
                bb[1] = Bs[(t * 8 + m + 4) * 72 + j * 8 + g];
                mma_tf32(acc[j], a, bb);
            }
        }
    }

    float b_lo = bias[r_lo], b_hi = bias[r_hi];
#pragma unroll
    for (int j = 0; j < 8; j++) {
        size_t olo = (size_t)r_lo * N_ + n0 + j * 8 + 2 * m;
        size_t ohi = (size_t)r_hi * N_ + n0 + j * 8 + 2 * m;
        float2 vlo; vlo.x = acc[j][0] + b_lo; vlo.y = acc[j][1] + b_lo;
        float2 vhi; vhi.x = acc[j][2] + b_hi; vhi.y = acc[j][3] + b_hi;
        if (resb) {
            float2 rl = *(const float2*)&resb[olo];
            float2 rh = *(const float2*)&resb[ohi];
            vlo.x += rl.x; vlo.y += rl.y;
            vhi.x += rh.x; vhi.y += rh.y;
        }
        *(float2*)&Outb[olo] = vlo;
        *(float2*)&Outb[ohi] = vhi;
    }
}

// ---------------------------------------------------------------------------
// Flash attention: QK^T in tf32, softmax, P.V in bf16 with register-relay P
// (m16n8k16 accumulator layout == A-fragment layout; no P smem).
// K smem tf32 [d][key] stride 72; V smem bf16 [d][key] stride 72.
// ---------------------------------------------------------------------------
__global__ __launch_bounds__(128) void attn_k() {
    int qt = blockIdx.x, h = blockIdx.y, b = blockIdx.z;
    const float* qb = g_qkv + ((size_t)b * 3 * C_ + h * HD_) * N_;
    const float* kb = qb + (size_t)C_ * N_;
    const float* vb = qb + (size_t)2 * C_ * N_;

    __shared__ uint32_t Ks[64 * 72];          // tf32
    __shared__ uint32_t Vs[64 * 36];          // bf16 pairs: halfword stride 72

    int tid = threadIdx.x, w = tid >> 5, lane = tid & 31;
    int g = lane >> 2, m = lane & 3;
    int q0 = qt * 64;
    int ty = tid >> 4, tx = tid & 15;

    // Q A-fragments (tf32), scaled for log2-domain softmax
    const float qs = SCALE_ * LOG2E_;
    uint32_t Af[8][4];
    int qlo = q0 + w * 16 + g, qhi = qlo + 8;
#pragma unroll
    for (int t = 0; t < 8; t++) {
        int d0 = t * 8 + m;
        Af[t][0] = f2tf(qb[(size_t)d0 * N_ + qlo] * qs);
        Af[t][1] = f2tf(qb[(size_t)d0 * N_ + qhi] * qs);
        Af[t][2] = f2tf(qb[(size_t)(d0 + 4) * N_ + qlo] * qs);
        Af[t][3] = f2tf(qb[(size_t)(d0 + 4) * N_ + qhi] * qs);
    }

    float O[8][4];
#pragma unroll
    for (int j = 0; j < 8; j++)
#pragma unroll
        for (int i = 0; i < 4; i++) O[j][i] = 0.f;
    float mlo = -1e30f, mhi = -1e30f, slo = 0.f, shi = 0.f;

    for (int k0t = 0; k0t < N_; k0t += 64) {
        __syncthreads();
        // Load K (tf32) and V (bf16) tiles, d-major
#pragma unroll
        for (int r = 0; r < 8; r++) {
            int d = ty + r * 8;
            float4 kv = *(const float4*)&kb[(size_t)d * N_ + k0t + tx * 4];
            float4 vv = *(const float4*)&vb[(size_t)d * N_ + k0t + tx * 4];
            uint4 ku; ku.x = f2tf(kv.x); ku.y = f2tf(kv.y); ku.z = f2tf(kv.z); ku.w = f2tf(kv.w);
            *(uint4*)&Ks[d * 72 + tx * 4] = ku;
            uint2 vp; vp.x = bf16x2(vv.x, vv.y); vp.y = bf16x2(vv.z, vv.w);
            *(uint2*)&Vs[d * 36 + tx * 2] = vp;
        }
        __syncthreads();

        // S = Q K^T  (tf32; warp: 16q x 64k)
        float S[8][4];
#pragma unroll
        for (int j = 0; j < 8; j++) {
            S[j][0] = S[j][1] = S[j][2] = S[j][3] = 0.f;
#pragma unroll
            for (int t = 0; t < 8; t++) {
                uint32_t bf[2];
                bf[0] = Ks[(t * 8 + m) * 72 + j * 8 + g];
                bf[1] = Ks[(t * 8 + m + 4) * 72 + j * 8 + g];
                mma_tf32(S[j], Af[t], bf);
            }
        }

        // Online softmax (log2 domain); build bf16 P fragments in registers
        float tlo = -1e30f, thi = -1e30f;
#pragma unroll
        for (int j = 0; j < 8; j++) {
            tlo = fmaxf(tlo, fmaxf(S[j][0], S[j][1]));
            thi = fmaxf(thi, fmaxf(S[j][2], S[j][3]));
        }
#pragma unroll
        for (int o = 1; o <= 2; o <<= 1) {
            tlo = fmaxf(tlo, __shfl_xor_sync(0xffffffffu, tlo, o));
            thi = fmaxf(thi, __shfl_xor_sync(0xffffffffu, thi, o));
        }
        float nlo = fmaxf(mlo, tlo), nhi = fmaxf(mhi, thi);
        float clo = ex2f(mlo - nlo), chi = ex2f(mhi - nhi);
        mlo = nlo; mhi = nhi;
        float ssl = 0.f, ssh = 0.f;
        uint32_t Pf[8][2];
#pragma unroll
        for (int j = 0; j < 8; j++) {
            float p0 = ex2f(S[j][0] - nlo);
            float p1 = ex2f(S[j][1] - nlo);
            float p2 = ex2f(S[j][2] - nhi);
            float p3 = ex2f(S[j][3] - nhi);
            ssl += p0 + p1; ssh += p2 + p3;
            O[j][0] *= clo; O[j][1] *= clo; O[j][2] *= chi; O[j][3] *= chi;
            Pf[j][0] = bf16x2(p0, p1);
            Pf[j][1] = bf16x2(p2, p3);
        }
#pragma unroll
        for (int o = 1; o <= 2; o <<= 1) {
            ssl += __shfl_xor_sync(0xffffffffu, ssl, o);
            ssh += __shfl_xor_sync(0xffffffffu, ssh, o);
        }
        slo = slo * clo + ssl;
        shi = shi * chi + ssh;

        // O += P @ V  (bf16, m16n8k16; k-chunks of 16 keys)
#pragma unroll
        for (int t = 0; t < 4; t++) {
            uint32_t Ap[4];
            Ap[0] = Pf[2 * t][0];
            Ap[1] = Pf[2 * t][1];
            Ap[2] = Pf[2 * t + 1][0];
            Ap[3] = Pf[2 * t + 1][1];
#pragma unroll
            for (int j = 0; j < 8; j++) {
                uint32_t bf[2];
                // V[d = j*8+g][key = 16t + 2m (+1)] and [key +8 (+9)]
                bf[0] = Vs[(j * 8 + g) * 36 + 8 * t + m];
                bf[1] = Vs[(j * 8 + g) * 36 + 8 * t + m + 4];
                mma_bf16(O[j], Ap, bf);
            }
        }
    }

    // Epilogue: normalize, write c-major for proj GEMM
    float* aob = g_ao + ((size_t)b * C_ + h * HD_) * N_;
    float ilo = 1.f / slo, ihi = 1.f / shi;
#pragma unroll
    for (int j = 0; j < 8; j++) {
        int d = j * 8 + 2 * m;
        aob[(size_t)d * N_ + qlo]       = O[j][0] * ilo;
        aob[(size_t)(d + 1) * N_ + qlo] = O[j][1] * ilo;
        aob[(size_t)d * N_ + qhi]       = O[j][2] * ihi;
        aob[(size_t)(d + 1) * N_ + qhi] = O[j][3] * ihi;
    }
}

// ---------------------------------------------------------------------------
// Launch sequence
// ---------------------------------------------------------------------------
extern "C" void kernel_launch(void* const* d_in, const int* in_sizes, int n_in,
                              void* d_out, int out_size) {
    const float* x    = (const float*)d_in[0];
    const float* gw   = (const float*)d_in[1];
    const float* gb   = (const float*)d_in[2];
    const float* qkvw = (const float*)d_in[3];
    const float* qkvb = (const float*)d_in[4];
    const float* pw   = (const float*)d_in[5];
    const float* pb   = (const float*)d_in[6];
    float* out = (float*)d_out;

    float *hn, *qkv, *ao;
    cudaGetSymbolAddress((void**)&hn,  g_hn);
    cudaGetSymbolAddress((void**)&qkv, g_qkv);
    cudaGetSymbolAddress((void**)&ao,  g_ao);

    gn_stats_k<<<B_ * NG_, 256>>>(x);
    gn_apply_k<<<(B_ * C_ * N_ / 4) / 256, 256>>>(x, gw, gb);
    {
        dim3 g(N_ / 64, (3 * C_) / 64, B_);
        sgemm_tc<<<g, 128>>>(qkvw, hn, qkvb, nullptr, qkv, 3 * C_, C_);
    }
    {
        dim3 g(N_ / 64, NH_, B_);
        attn_k<<<g, 128>>>();
    }
    {
        dim3 g(N_ / 64, C_ / 64, B_);
        sgemm_tc<<<g, 128>>>(pw, ao, pb, x, out, C_, C_);
    }
}

// round 5
// speedup vs baseline: 4.6694x; 1.1762x over previous
#include <cuda_runtime.h>
#include <cstdint>

// Problem constants
#define B_   4
#define C_   256
#define N_   4096          // H*W = 64*64
#define NH_  4
#define HD_  64
#define NG_  8
#define CPG_ 32
#define EPS_ 1e-5f
#define SCALE_ 0.125f      // HD^-0.5
#define LOG2E_ 1.4426950408889634f

// Scratch
__device__ float    g_hn  [(size_t)B_ * C_     * N_];
__device__ float    g_qkv [(size_t)B_ * 3 * C_ * N_];
__device__ float    g_ao  [(size_t)B_ * C_     * N_];
__device__ uint16_t g_vb  [(size_t)B_ * C_     * N_];   // V pre-converted to bf16
__device__ float    g_stats[B_ * NG_ * 2];

// ---------------------------------------------------------------------------
// helpers
// ---------------------------------------------------------------------------
__device__ __forceinline__ uint32_t f2tf(float f) {
    uint32_t u;
    asm("cvt.rna.tf32.f32 %0, %1;" : "=r"(u) : "f"(f));
    return u;
}
__device__ __forceinline__ float ex2f(float x) {
    float y;
    asm("ex2.approx.ftz.f32 %0, %1;" : "=f"(y) : "f"(x));
    return y;
}
__device__ __forceinline__ uint32_t bf16x2(float a, float b) {   // {lo:a, hi:b}
    uint32_t r;
    asm("cvt.rn.bf16x2.f32 %0, %1, %2;" : "=r"(r) : "f"(b), "f"(a));
    return r;
}
__device__ __forceinline__ uint32_t smem_u32(const void* p) {
    uint32_t a;
    asm("{ .reg .u64 t; cvta.to.shared.u64 t, %1; cvt.u32.u64 %0, t; }" : "=r"(a) : "l"(p));
    return a;
}
__device__ __forceinline__ void cpa16(uint32_t s, const void* g) {
    asm volatile("cp.async.cg.shared.global [%0], [%1], 16;" :: "r"(s), "l"(g));
}
__device__ __forceinline__ void cpa_commit() {
    asm volatile("cp.async.commit_group;");
}
__device__ __forceinline__ void cpa_wait1() {
    asm volatile("cp.async.wait_group 1;");
}
__device__ __forceinline__ void cpa_wait0() {
    asm volatile("cp.async.wait_group 0;");
}
__device__ __forceinline__ void mma_tf32(float* d, const uint32_t* a, const uint32_t* b) {
    asm("mma.sync.aligned.m16n8k8.row.col.f32.tf32.tf32.f32 "
        "{%0,%1,%2,%3}, {%4,%5,%6,%7}, {%8,%9}, {%0,%1,%2,%3};"
        : "+f"(d[0]), "+f"(d[1]), "+f"(d[2]), "+f"(d[3])
        : "r"(a[0]), "r"(a[1]), "r"(a[2]), "r"(a[3]), "r"(b[0]), "r"(b[1]));
}
__device__ __forceinline__ void mma_bf16(float* d, const uint32_t* a, const uint32_t* b) {
    asm("mma.sync.aligned.m16n8k16.row.col.f32.bf16.bf16.f32 "
        "{%0,%1,%2,%3}, {%4,%5,%6,%7}, {%8,%9}, {%0,%1,%2,%3};"
        : "+f"(d[0]), "+f"(d[1]), "+f"(d[2]), "+f"(d[3])
        : "r"(a[0]), "r"(a[1]), "r"(a[2]), "r"(a[3]), "r"(b[0]), "r"(b[1]));
}

// ---------------------------------------------------------------------------
// GroupNorm statistics
// ---------------------------------------------------------------------------
__global__ void gn_stats_k(const float* __restrict__ x) {
    int bg = blockIdx.x;
    const float4* base = (const float4*)(x + (size_t)bg * CPG_ * N_);
    int tid = threadIdx.x;
    float s = 0.f, s2 = 0.f;
    const int nv = CPG_ * N_ / 4;
    for (int i = tid; i < nv; i += 256) {
        float4 v = base[i];
        s  += v.x + v.y + v.z + v.w;
        s2 += v.x * v.x + v.y * v.y + v.z * v.z + v.w * v.w;
    }
    __shared__ float rs[256], rq[256];
    rs[tid] = s; rq[tid] = s2;
    __syncthreads();
    for (int o = 128; o > 0; o >>= 1) {
        if (tid < o) { rs[tid] += rs[tid + o]; rq[tid] += rq[tid + o]; }
        __syncthreads();
    }
    if (tid == 0) {
        const float invn = 1.f / (float)(CPG_ * N_);
        float mean = rs[0] * invn;
        float var  = rq[0] * invn - mean * mean;
        g_stats[bg * 2 + 0] = mean;
        g_stats[bg * 2 + 1] = rsqrtf(var + EPS_);
    }
}

// ---------------------------------------------------------------------------
// GroupNorm apply
// ---------------------------------------------------------------------------
__global__ void gn_apply_k(const float* __restrict__ x,
                           const float* __restrict__ gw,
                           const float* __restrict__ gb) {
    int i = blockIdx.x * 256 + threadIdx.x;
    size_t e = (size_t)i * 4;
    int c  = (int)((e >> 12) & (C_ - 1));
    int bg = (int)(e >> 17);
    float mean = g_stats[bg * 2 + 0];
    float rstd = g_stats[bg * 2 + 1];
    float ga = gw[c] * rstd;
    float be = gb[c] - mean * ga;
    float4 v = ((const float4*)x)[i];
    float4 o;
    o.x = v.x * ga + be;
    o.y = v.y * ga + be;
    o.z = v.z * ga + be;
    o.w = v.w * ga + be;
    ((float4*)g_hn)[i] = o;
}

// ---------------------------------------------------------------------------
// V -> bf16 repack: g_vb[(b*NH+h)*HD + d][n] = bf16(g_qkv V part)
// ---------------------------------------------------------------------------
__global__ void v2bf_k() {
    int bh = blockIdx.y;                 // b*NH + h
    int b = bh >> 2, h = bh & 3;
    size_t iin  = ((size_t)b * 3 * C_ + 2 * C_ + h * HD_) * N_;
    size_t iout = ((size_t)bh * HD_) * N_;
    int i = blockIdx.x * 256 + threadIdx.x;      // float4 idx over HD_*N_/4
    float4 v = *(const float4*)&g_qkv[iin + (size_t)i * 4];
    uint2 o;
    o.x = bf16x2(v.x, v.y);
    o.y = bf16x2(v.z, v.w);
    *(uint2*)(g_vb + iout + (size_t)i * 4) = o;
}

// ---------------------------------------------------------------------------
// tf32 tensor-core GEMM with cp.async double buffer.
// CTA 64m x 64n, 4 warps; B tile raw fp32 in smem stride 72.
// ---------------------------------------------------------------------------
__global__ __launch_bounds__(128) void sgemm_tc(const float* __restrict__ W,
                                                const float* __restrict__ In,
                                                const float* __restrict__ bias,
                                                const float* __restrict__ res,
                                                float* __restrict__ Out,
                                                int M, int K) {
    int b  = blockIdx.z;
    const float* Inb  = In + (size_t)b * K * N_;
    float*       Outb = Out + (size_t)b * M * N_;
    const float* resb = res ? res + (size_t)b * M * N_ : nullptr;
    int m0 = blockIdx.y * 64, n0 = blockIdx.x * 64;

    __shared__ float Bs[2][32 * 72];

    int tid = threadIdx.x, w = tid >> 5, lane = tid & 31;
    int g = lane >> 2, m = lane & 3;
    int r_lo = m0 + w * 16 + g, r_hi = r_lo + 8;
    uint32_t bsm[2] = { smem_u32(&Bs[0][0]), smem_u32(&Bs[1][0]) };

    float acc[8][4];
#pragma unroll
    for (int j = 0; j < 8; j++)
#pragma unroll
        for (int i = 0; i < 4; i++) acc[j][i] = 0.f;

    const int NS = K / 32;
    // prologue: slab 0
    {
#pragma unroll
        for (int it = 0; it < 4; it++) {
            int idx = it * 128 + tid;
            int d = idx >> 4, c = idx & 15;
            cpa16(bsm[0] + (uint32_t)(d * 72 + c * 4) * 4,
                  Inb + (size_t)d * N_ + n0 + c * 4);
        }
        cpa_commit();
    }
    for (int ks = 0; ks < NS; ks++) {
        if (ks + 1 < NS) {
            int s = (ks + 1) & 1, k0 = (ks + 1) * 32;
#pragma unroll
            for (int it = 0; it < 4; it++) {
                int idx = it * 128 + tid;
                int d = idx >> 4, c = idx & 15;
                cpa16(bsm[s] + (uint32_t)(d * 72 + c * 4) * 4,
                      Inb + (size_t)(k0 + d) * N_ + n0 + c * 4);
            }
            cpa_commit();
            cpa_wait1();
        } else {
            cpa_wait0();
        }
        __syncthreads();
        const float* Bc = &Bs[ks & 1][0];
        int k0 = ks * 32;
#pragma unroll
        for (int t = 0; t < 4; t++) {
            uint32_t a[4];
            a[0] = f2tf(W[(size_t)r_lo * K + k0 + t * 8 + m]);
            a[1] = f2tf(W[(size_t)r_hi * K + k0 + t * 8 + m]);
            a[2] = f2tf(W[(size_t)r_lo * K + k0 + t * 8 + m + 4]);
            a[3] = f2tf(W[(size_t)r_hi * K + k0 + t * 8 + m + 4]);
#pragma unroll
            for (int j = 0; j < 8; j++) {
                uint32_t bb[2];
                bb[0] = __float_as_uint(Bc[(t * 8 + m) * 72 + j * 8 + g]);
                bb[1] = __float_as_uint(Bc[(t * 8 + m + 4) * 72 + j * 8 + g]);
                mma_tf32(acc[j], a, bb);
            }
        }
        __syncthreads();
    }

    float b_lo = bias[r_lo], b_hi = bias[r_hi];
#pragma unroll
    for (int j = 0; j < 8; j++) {
        size_t olo = (size_t)r_lo * N_ + n0 + j * 8 + 2 * m;
        size_t ohi = (size_t)r_hi * N_ + n0 + j * 8 + 2 * m;
        float2 vlo; vlo.x = acc[j][0] + b_lo; vlo.y = acc[j][1] + b_lo;
        float2 vhi; vhi.x = acc[j][2] + b_hi; vhi.y = acc[j][3] + b_hi;
        if (resb) {
            float2 rl = *(const float2*)&resb[olo];
            float2 rh = *(const float2*)&resb[ohi];
            vlo.x += rl.x; vlo.y += rl.y;
            vhi.x += rh.x; vhi.y += rh.y;
        }
        *(float2*)&Outb[olo] = vlo;
        *(float2*)&Outb[ohi] = vhi;
    }
}

// ---------------------------------------------------------------------------
// Flash attention: 2-stage cp.async pipeline.
// K tile raw fp32 (stride 72 words) -> tf32 MMA directly.
// V tile bf16 (pre-converted; halfword stride 72) -> register-relay P.V.
// ---------------------------------------------------------------------------
#define ATT_SMEM (2 * 64 * 72 * 4 + 2 * 64 * 72 * 2)   // 55296 B

__global__ __launch_bounds__(128, 4) void attn_k() {
    int qt = blockIdx.x, h = blockIdx.y, b = blockIdx.z;
    const float* qb = g_qkv + ((size_t)b * 3 * C_ + h * HD_) * N_;
    const float* kb = qb + (size_t)C_ * N_;
    const uint16_t* vbb = g_vb + ((size_t)(b * NH_ + h) * HD_) * N_;

    extern __shared__ float smraw[];
    float*    Ksb = smraw;                              // 2 x [64][72] fp32
    uint16_t* Vsb = (uint16_t*)(smraw + 2 * 64 * 72);   // 2 x [64][72] bf16
    uint32_t ksm[2] = { smem_u32(Ksb), smem_u32(Ksb + 64 * 72) };
    uint32_t vsm[2] = { smem_u32(Vsb), smem_u32(Vsb + 64 * 72) };

    int tid = threadIdx.x, w = tid >> 5, lane = tid & 31;
    int g = lane >> 2, m = lane & 3;
    int q0 = qt * 64;

    // prologue: issue tile 0 into stage 0
    {
#pragma unroll
        for (int it = 0; it < 8; it++) {
            int idx = it * 128 + tid;
            int d = idx >> 4, c = idx & 15;
            cpa16(ksm[0] + (uint32_t)(d * 72 + c * 4) * 4, kb + (size_t)d * N_ + c * 4);
        }
#pragma unroll
        for (int it = 0; it < 4; it++) {
            int idx = it * 128 + tid;
            int d = idx >> 3, c = idx & 7;
            cpa16(vsm[0] + (uint32_t)(d * 144 + c * 16), vbb + (size_t)d * N_ + c * 8);
        }
        cpa_commit();
    }

    // Q A-fragments (tf32, RNA), scaled for log2-domain softmax
    const float qs = SCALE_ * LOG2E_;
    uint32_t Af[8][4];
    int qlo = q0 + w * 16 + g, qhi = qlo + 8;
#pragma unroll
    for (int t = 0; t < 8; t++) {
        int d0 = t * 8 + m;
        Af[t][0] = f2tf(qb[(size_t)d0 * N_ + qlo] * qs);
        Af[t][1] = f2tf(qb[(size_t)d0 * N_ + qhi] * qs);
        Af[t][2] = f2tf(qb[(size_t)(d0 + 4) * N_ + qlo] * qs);
        Af[t][3] = f2tf(qb[(size_t)(d0 + 4) * N_ + qhi] * qs);
    }

    float O[8][4];
#pragma unroll
    for (int j = 0; j < 8; j++)
#pragma unroll
        for (int i = 0; i < 4; i++) O[j][i] = 0.f;
    float mlo = -1e30f, mhi = -1e30f, slo = 0.f, shi = 0.f;

    const int NT = N_ / 64;
    for (int kt = 0; kt < NT; kt++) {
        if (kt + 1 < NT) {
            int s = (kt + 1) & 1, k0t = (kt + 1) * 64;
#pragma unroll
            for (int it = 0; it < 8; it++) {
                int idx = it * 128 + tid;
                int d = idx >> 4, c = idx & 15;
                cpa16(ksm[s] + (uint32_t)(d * 72 + c * 4) * 4,
                      kb + (size_t)d * N_ + k0t + c * 4);
            }
#pragma unroll
            for (int it = 0; it < 4; it++) {
                int idx = it * 128 + tid;
                int d = idx >> 3, c = idx & 7;
                cpa16(vsm[s] + (uint32_t)(d * 144 + c * 16),
                      vbb + (size_t)d * N_ + k0t + c * 8);
            }
            cpa_commit();
            cpa_wait1();
        } else {
            cpa_wait0();
        }
        __syncthreads();

        const float*    Ks = Ksb + (kt & 1) * 64 * 72;
        const uint32_t* Vs = (const uint32_t*)(Vsb + (kt & 1) * 64 * 72);

        // S = Q K^T  (tf32; fp32 K bits fed directly)
        float S[8][4];
#pragma unroll
        for (int j = 0; j < 8; j++) {
            S[j][0] = S[j][1] = S[j][2] = S[j][3] = 0.f;
#pragma unroll
            for (int t = 0; t < 8; t++) {
                uint32_t bf[2];
                bf[0] = __float_as_uint(Ks[(t * 8 + m) * 72 + j * 8 + g]);
                bf[1] = __float_as_uint(Ks[(t * 8 + m + 4) * 72 + j * 8 + g]);
                mma_tf32(S[j], Af[t], bf);
            }
        }

        // Online softmax (log2 domain); P as bf16 fragments in registers
        float tlo = -1e30f, thi = -1e30f;
#pragma unroll
        for (int j = 0; j < 8; j++) {
            tlo = fmaxf(tlo, fmaxf(S[j][0], S[j][1]));
            thi = fmaxf(thi, fmaxf(S[j][2], S[j][3]));
        }
#pragma unroll
        for (int o = 1; o <= 2; o <<= 1) {
            tlo = fmaxf(tlo, __shfl_xor_sync(0xffffffffu, tlo, o));
            thi = fmaxf(thi, __shfl_xor_sync(0xffffffffu, thi, o));
        }
        float nlo = fmaxf(mlo, tlo), nhi = fmaxf(mhi, thi);
        float clo = ex2f(mlo - nlo), chi = ex2f(mhi - nhi);
        mlo = nlo; mhi = nhi;
        float ssl = 0.f, ssh = 0.f;
        uint32_t Pf[8][2];
#pragma unroll
        for (int j = 0; j < 8; j++) {
            float p0 = ex2f(S[j][0] - nlo);
            float p1 = ex2f(S[j][1] - nlo);
            float p2 = ex2f(S[j][2] - nhi);
            float p3 = ex2f(S[j][3] - nhi);
            ssl += p0 + p1; ssh += p2 + p3;
            O[j][0] *= clo; O[j][1] *= clo; O[j][2] *= chi; O[j][3] *= chi;
            Pf[j][0] = bf16x2(p0, p1);
            Pf[j][1] = bf16x2(p2, p3);
        }
#pragma unroll
        for (int o = 1; o <= 2; o <<= 1) {
            ssl += __shfl_xor_sync(0xffffffffu, ssl, o);
            ssh += __shfl_xor_sync(0xffffffffu, ssh, o);
        }
        slo = slo * clo + ssl;
        shi = shi * chi + ssh;

        // O += P @ V  (bf16 m16n8k16, register-relay P)
#pragma unroll
        for (int t = 0; t < 4; t++) {
            uint32_t Ap[4];
            Ap[0] = Pf[2 * t][0];
            Ap[1] = Pf[2 * t][1];
            Ap[2] = Pf[2 * t + 1][0];
            Ap[3] = Pf[2 * t + 1][1];
#pragma unroll
            for (int j = 0; j < 8; j++) {
                uint32_t bf[2];
                bf[0] = Vs[(j * 8 + g) * 36 + 8 * t + m];
                bf[1] = Vs[(j * 8 + g) * 36 + 8 * t + m + 4];
                mma_bf16(O[j], Ap, bf);
            }
        }
        __syncthreads();    // all reads of this stage done before it is refilled
    }

    // Epilogue: normalize, write c-major for proj GEMM
    float* aob = g_ao + ((size_t)b * C_ + h * HD_) * N_;
    float ilo = 1.f / slo, ihi = 1.f / shi;
#pragma unroll
    for (int j = 0; j < 8; j++) {
        int d = j * 8 + 2 * m;
        aob[(size_t)d * N_ + qlo]       = O[j][0] * ilo;
        aob[(size_t)(d + 1) * N_ + qlo] = O[j][1] * ilo;
        aob[(size_t)d * N_ + qhi]       = O[j][2] * ihi;
        aob[(size_t)(d + 1) * N_ + qhi] = O[j][3] * ihi;
    }
}

// ---------------------------------------------------------------------------
// Launch sequence
// ---------------------------------------------------------------------------
extern "C" void kernel_launch(void* const* d_in, const int* in_sizes, int n_in,
                              void* d_out, int out_size) {
    const float* x    = (const float*)d_in[0];
    const float* gw   = (const float*)d_in[1];
    const float* gb   = (const float*)d_in[2];
    const float* qkvw = (const float*)d_in[3];
    const float* qkvb = (const float*)d_in[4];
    const float* pw   = (const float*)d_in[5];
    const float* pb   = (const float*)d_in[6];
    float* out = (float*)d_out;

    float *hn, *qkv, *ao;
    cudaGetSymbolAddress((void**)&hn,  g_hn);
    cudaGetSymbolAddress((void**)&qkv, g_qkv);
    cudaGetSymbolAddress((void**)&ao,  g_ao);

    gn_stats_k<<<B_ * NG_, 256>>>(x);
    gn_apply_k<<<(B_ * C_ * N_ / 4) / 256, 256>>>(x, gw, gb);
    {
        dim3 g(N_ / 64, (3 * C_) / 64, B_);
        sgemm_tc<<<g, 128>>>(qkvw, hn, qkvb, nullptr, qkv, 3 * C_, C_);
    }
    {
        dim3 g((HD_ * N_ / 4) / 256, B_ * NH_);
        v2bf_k<<<g, 256>>>();
    }
    cudaFuncSetAttribute(attn_k, cudaFuncAttributeMaxDynamicSharedMemorySize, ATT_SMEM);
    {
        dim3 g(N_ / 64, NH_, B_);
        attn_k<<<g, 128, ATT_SMEM>>>();
    }
    {
        dim3 g(N_ / 64, C_ / 64, B_);
        sgemm_tc<<<g, 128>>>(pw, ao, pb, x, out, C_, C_);
    }
}

// round 7
// speedup vs baseline: 6.0156x; 1.2883x over previous
#include <cuda_runtime.h>
#include <cuda_fp16.h>
#include <cstdint>

// Problem constants
#define B_   4
#define C_   256
#define N_   4096          // H*W = 64*64
#define NH_  4
#define HD_  64
#define NG_  8
#define CPG_ 32
#define EPS_ 1e-5f
#define SCALE_ 0.125f      // HD^-0.5
#define LOG2E_ 1.4426950408889634f

// Scratch
__device__ float    g_hn  [(size_t)B_ * C_     * N_];
__device__ float    g_qkv [(size_t)B_ * 3 * C_ * N_];
__device__ float    g_ao  [(size_t)B_ * C_     * N_];
__device__ uint16_t g_kh  [(size_t)B_ * C_     * N_];   // K fp16, key-major [bh][key][d]
__device__ uint16_t g_vh  [(size_t)B_ * C_     * N_];   // V fp16, d-major  [bh][d][key]
__device__ float    g_stats[B_ * NG_ * 2];

// ---------------------------------------------------------------------------
// helpers
// ---------------------------------------------------------------------------
__device__ __forceinline__ uint32_t f2tf(float f) {
    uint32_t u;
    asm("cvt.rna.tf32.f32 %0, %1;" : "=r"(u) : "f"(f));
    return u;
}
__device__ __forceinline__ float ex2f(float x) {
    float y;
    asm("ex2.approx.ftz.f32 %0, %1;" : "=f"(y) : "f"(x));
    return y;
}
__device__ __forceinline__ uint32_t f16x2(float a, float b) {   // {lo:a, hi:b}
    uint32_t r;
    asm("cvt.rn.f16x2.f32 %0, %1, %2;" : "=r"(r) : "f"(b), "f"(a));
    return r;
}
__device__ __forceinline__ uint32_t smem_u32(const void* p) {
    uint32_t a;
    asm("{ .reg .u64 t; cvta.to.shared.u64 t, %1; cvt.u32.u64 %0, t; }" : "=r"(a) : "l"(p));
    return a;
}
__device__ __forceinline__ void cpa16(uint32_t s, const void* g) {
    asm volatile("cp.async.cg.shared.global [%0], [%1], 16;" :: "r"(s), "l"(g));
}
__device__ __forceinline__ void cpa_commit() { asm volatile("cp.async.commit_group;"); }
__device__ __forceinline__ void cpa_wait1()  { asm volatile("cp.async.wait_group 1;"); }
__device__ __forceinline__ void cpa_wait0()  { asm volatile("cp.async.wait_group 0;"); }

__device__ __forceinline__ void mma_tf32(float* d, const uint32_t* a, const uint32_t* b) {
    asm("mma.sync.aligned.m16n8k8.row.col.f32.tf32.tf32.f32 "
        "{%0,%1,%2,%3}, {%4,%5,%6,%7}, {%8,%9}, {%0,%1,%2,%3};"
        : "+f"(d[0]), "+f"(d[1]), "+f"(d[2]), "+f"(d[3])
        : "r"(a[0]), "r"(a[1]), "r"(a[2]), "r"(a[3]), "r"(b[0]), "r"(b[1]));
}
__device__ __forceinline__ void mma_f16(float* d, const uint32_t* a, const uint32_t* b) {
    asm("mma.sync.aligned.m16n8k16.row.col.f32.f16.f16.f32 "
        "{%0,%1,%2,%3}, {%4,%5,%6,%7}, {%8,%9}, {%0,%1,%2,%3};"
        : "+f"(d[0]), "+f"(d[1]), "+f"(d[2]), "+f"(d[3])
        : "r"(a[0]), "r"(a[1]), "r"(a[2]), "r"(a[3]), "r"(b[0]), "r"(b[1]));
}

// ---------------------------------------------------------------------------
// GroupNorm statistics
// ---------------------------------------------------------------------------
__global__ void gn_stats_k(const float* __restrict__ x) {
    int bg = blockIdx.x;
    const float4* base = (const float4*)(x + (size_t)bg * CPG_ * N_);
    int tid = threadIdx.x;
    float s = 0.f, s2 = 0.f;
    const int nv = CPG_ * N_ / 4;
    for (int i = tid; i < nv; i += 256) {
        float4 v = base[i];
        s  += v.x + v.y + v.z + v.w;
        s2 += v.x * v.x + v.y * v.y + v.z * v.z + v.w * v.w;
    }
    __shared__ float rs[256], rq[256];
    rs[tid] = s; rq[tid] = s2;
    __syncthreads();
    for (int o = 128; o > 0; o >>= 1) {
        if (tid < o) { rs[tid] += rs[tid + o]; rq[tid] += rq[tid + o]; }
        __syncthreads();
    }
    if (tid == 0) {
        const float invn = 1.f / (float)(CPG_ * N_);
        float mean = rs[0] * invn;
        float var  = rq[0] * invn - mean * mean;
        g_stats[bg * 2 + 0] = mean;
        g_stats[bg * 2 + 1] = rsqrtf(var + EPS_);
    }
}

// ---------------------------------------------------------------------------
// GroupNorm apply
// ---------------------------------------------------------------------------
__global__ void gn_apply_k(const float* __restrict__ x,
                           const float* __restrict__ gw,
                           const float* __restrict__ gb) {
    int i = blockIdx.x * 256 + threadIdx.x;
    size_t e = (size_t)i * 4;
    int c  = (int)((e >> 12) & (C_ - 1));
    int bg = (int)(e >> 17);
    float mean = g_stats[bg * 2 + 0];
    float rstd = g_stats[bg * 2 + 1];
    float ga = gw[c] * rstd;
    float be = gb[c] - mean * ga;
    float4 v = ((const float4*)x)[i];
    float4 o;
    o.x = v.x * ga + be;
    o.y = v.y * ga + be;
    o.z = v.z * ga + be;
    o.w = v.w * ga + be;
    ((float4*)g_hn)[i] = o;
}

// ---------------------------------------------------------------------------
// Repack: K -> fp16 key-major [bh][key][64] (transpose via smem tile);
//         V -> fp16 d-major  [bh][d][N]    (straight convert).
// Grid: (N_/64, B_*NH_), 256 threads. Tile = 64 keys x 64 d.
// ---------------------------------------------------------------------------
__global__ void repack_kv_k() {
    int bh = blockIdx.y;
    int b = bh >> 2, h = bh & 3;
    const float* kb = g_qkv + ((size_t)b * 3 * C_ + C_ + h * HD_) * N_;
    const float* vb = g_qkv + ((size_t)b * 3 * C_ + 2 * C_ + h * HD_) * N_;
    int key0 = blockIdx.x * 64;
    int t = threadIdx.x;

    __shared__ __half kt[64][65];

    int key = t & 63, dg = t >> 6;          // dg = 0..3
#pragma unroll
    for (int i = 0; i < 16; i++) {
        int d = dg * 16 + i;
        float kvv = kb[(size_t)d * N_ + key0 + key];
        float vvv = vb[(size_t)d * N_ + key0 + key];
        kt[d][key] = __float2half(kvv);
        g_vh[((size_t)bh * HD_ + d) * N_ + key0 + key] = __half_as_ushort(__float2half(vvv));
    }
    __syncthreads();

    // write K rows [key][d] coalesced: thread = (key = t>>2, chunk c = t&3 of 16 halfwords)
    int okey = t >> 2, c = t & 3;
    uint32_t pk[8];
#pragma unroll
    for (int u = 0; u < 8; u++) {
        __half2 h2 = __halves2half2(kt[c * 16 + 2 * u][okey], kt[c * 16 + 2 * u + 1][okey]);
        pk[u] = *(uint32_t*)&h2;
    }
    uint16_t* orow = g_kh + ((size_t)bh * N_ + key0 + okey) * HD_ + c * 16;
    *(uint4*)(orow)     = *(uint4*)&pk[0];
    *(uint4*)(orow + 8) = *(uint4*)&pk[4];
}

// ---------------------------------------------------------------------------
// tf32 tensor-core GEMM with cp.async double buffer.
// ---------------------------------------------------------------------------
__global__ __launch_bounds__(128) void sgemm_tc(const float* __restrict__ W,
                                                const float* __restrict__ In,
                                                const float* __restrict__ bias,
                                                const float* __restrict__ res,
                                                float* __restrict__ Out,
                                                int M, int K) {
    int b  = blockIdx.z;
    const float* Inb  = In + (size_t)b * K * N_;
    float*       Outb = Out + (size_t)b * M * N_;
    const float* resb = res ? res + (size_t)b * M * N_ : nullptr;
    int m0 = blockIdx.y * 64, n0 = blockIdx.x * 64;

    __shared__ float Bs[2][32 * 72];

    int tid = threadIdx.x, w = tid >> 5, lane = tid & 31;
    int g = lane >> 2, m = lane & 3;
    int r_lo = m0 + w * 16 + g, r_hi = r_lo + 8;
    uint32_t bsm[2] = { smem_u32(&Bs[0][0]), smem_u32(&Bs[1][0]) };

    float acc[8][4];
#pragma unroll
    for (int j = 0; j < 8; j++)
#pragma unroll
        for (int i = 0; i < 4; i++) acc[j][i] = 0.f;

    const int NS = K / 32;
    {
#pragma unroll
        for (int it = 0; it < 4; it++) {
            int idx = it * 128 + tid;
            int d = idx >> 4, c = idx & 15;
            cpa16(bsm[0] + (uint32_t)(d * 72 + c * 4) * 4,
                  Inb + (size_t)d * N_ + n0 + c * 4);
        }
        cpa_commit();
    }
    for (int ks = 0; ks < NS; ks++) {
        if (ks + 1 < NS) {
            int s = (ks + 1) & 1, k0 = (ks + 1) * 32;
#pragma unroll
            for (int it = 0; it < 4; it++) {
                int idx = it * 128 + tid;
                int d = idx >> 4, c = idx & 15;
                cpa16(bsm[s] + (uint32_t)(d * 72 + c * 4) * 4,
                      Inb + (size_t)(k0 + d) * N_ + n0 + c * 4);
            }
            cpa_commit();
            cpa_wait1();
        } else {
            cpa_wait0();
        }
        __syncthreads();
        const float* Bc = &Bs[ks & 1][0];
        int k0 = ks * 32;
#pragma unroll
        for (int t = 0; t < 4; t++) {
            uint32_t a[4];
            a[0] = f2tf(W[(size_t)r_lo * K + k0 + t * 8 + m]);
            a[1] = f2tf(W[(size_t)r_hi * K + k0 + t * 8 + m]);
            a[2] = f2tf(W[(size_t)r_lo * K + k0 + t * 8 + m + 4]);
            a[3] = f2tf(W[(size_t)r_hi * K + k0 + t * 8 + m + 4]);
#pragma unroll
            for (int j = 0; j < 8; j++) {
                uint32_t bb[2];
                bb[0] = __float_as_uint(Bc[(t * 8 + m) * 72 + j * 8 + g]);
                bb[1] = __float_as_uint(Bc[(t * 8 + m + 4) * 72 + j * 8 + g]);
                mma_tf32(acc[j], a, bb);
            }
        }
        __syncthreads();
    }

    float b_lo = bias[r_lo], b_hi = bias[r_hi];
#pragma unroll
    for (int j = 0; j < 8; j++) {
        size_t olo = (size_t)r_lo * N_ + n0 + j * 8 + 2 * m;
        size_t ohi = (size_t)r_hi * N_ + n0 + j * 8 + 2 * m;
        float2 vlo; vlo.x = acc[j][0] + b_lo; vlo.y = acc[j][1] + b_lo;
        float2 vhi; vhi.x = acc[j][2] + b_hi; vhi.y = acc[j][3] + b_hi;
        if (resb) {
            float2 rl = *(const float2*)&resb[olo];
            float2 rh = *(const float2*)&resb[ohi];
            vlo.x += rl.x; vlo.y += rl.y;
            vhi.x += rh.x; vhi.y += rh.y;
        }
        *(float2*)&Outb[olo] = vlo;
        *(float2*)&Outb[ohi] = vhi;
    }
}

// ---------------------------------------------------------------------------
// Flash attention, full fp16 MMA path.
// K smem [key][72 halfwords] (from key-major fp16 global);
// V smem [d][72 halfwords]. Both conflict-free (bank = 4g + m).
// QK^T and P.V both m16n8k16.f16 with fp32 accum; register-relay P.
// 2-stage cp.async pipeline. 36 KB static smem.
// ---------------------------------------------------------------------------
__global__ __launch_bounds__(128, 4) void attn_k() {
    int qt = blockIdx.x, h = blockIdx.y, b = blockIdx.z;
    int bh = b * NH_ + h;
    const float*    qb  = g_qkv + ((size_t)b * 3 * C_ + h * HD_) * N_;
    const uint16_t* khb = g_kh + (size_t)bh * N_ * HD_;
    const uint16_t* vhb = g_vh + (size_t)bh * HD_ * N_;

    __shared__ uint16_t Kh[2][64 * 72];
    __shared__ uint16_t Vh[2][64 * 72];
    uint32_t ksm[2] = { smem_u32(Kh[0]), smem_u32(Kh[1]) };
    uint32_t vsm[2] = { smem_u32(Vh[0]), smem_u32(Vh[1]) };

    int tid = threadIdx.x, w = tid >> 5, lane = tid & 31;
    int g = lane >> 2, m = lane & 3;
    int q0 = qt * 64;

    // prologue: tile 0 into stage 0 (K: 64 rows x 8 chunks; V likewise)
    {
#pragma unroll
        for (int it = 0; it < 4; it++) {
            int idx = it * 128 + tid;
            int r = idx >> 3, c = idx & 7;
            cpa16(ksm[0] + (uint32_t)(r * 144 + c * 16), khb + (size_t)r * HD_ + c * 8);
        }
#pragma unroll
        for (int it = 0; it < 4; it++) {
            int idx = it * 128 + tid;
            int r = idx >> 3, c = idx & 7;
            cpa16(vsm[0] + (uint32_t)(r * 144 + c * 16), vhb + (size_t)r * N_ + c * 8);
        }
        cpa_commit();
    }

    // Q A-fragments (fp16), scaled for log2-domain softmax.
    // m16n8k16 A layout: a0={A[g][2m],A[g][2m+1]}, a1={A[g+8][..]},
    //                    a2={A[g][2m+8],A[g][2m+9]}, a3={A[g+8][..+8]}
    const float qs = SCALE_ * LOG2E_;
    uint32_t Aq[4][4];
    int qlo = q0 + w * 16 + g, qhi = qlo + 8;
#pragma unroll
    for (int t = 0; t < 4; t++) {
        int d0 = t * 16 + 2 * m;
        Aq[t][0] = f16x2(qb[(size_t)d0 * N_ + qlo] * qs,       qb[(size_t)(d0 + 1) * N_ + qlo] * qs);
        Aq[t][1] = f16x2(qb[(size_t)d0 * N_ + qhi] * qs,       qb[(size_t)(d0 + 1) * N_ + qhi] * qs);
        Aq[t][2] = f16x2(qb[(size_t)(d0 + 8) * N_ + qlo] * qs, qb[(size_t)(d0 + 9) * N_ + qlo] * qs);
        Aq[t][3] = f16x2(qb[(size_t)(d0 + 8) * N_ + qhi] * qs, qb[(size_t)(d0 + 9) * N_ + qhi] * qs);
    }

    float O[8][4];
#pragma unroll
    for (int j = 0; j < 8; j++)
#pragma unroll
        for (int i = 0; i < 4; i++) O[j][i] = 0.f;
    float mlo = -1e30f, mhi = -1e30f, slo = 0.f, shi = 0.f;

    const int NT = N_ / 64;
    for (int kt = 0; kt < NT; kt++) {
        if (kt + 1 < NT) {
            int s = (kt + 1) & 1, k0t = (kt + 1) * 64;
#pragma unroll
            for (int it = 0; it < 4; it++) {
                int idx = it * 128 + tid;
                int r = idx >> 3, c = idx & 7;
                cpa16(ksm[s] + (uint32_t)(r * 144 + c * 16),
                      khb + (size_t)(k0t + r) * HD_ + c * 8);
            }
#pragma unroll
            for (int it = 0; it < 4; it++) {
                int idx = it * 128 + tid;
                int r = idx >> 3, c = idx & 7;
                cpa16(vsm[s] + (uint32_t)(r * 144 + c * 16),
                      vhb + (size_t)r * N_ + k0t + c * 8);
            }
            cpa_commit();
            cpa_wait1();
        } else {
            cpa_wait0();
        }
        __syncthreads();

        const uint32_t* Kw = (const uint32_t*)Kh[kt & 1];
        const uint32_t* Vw = (const uint32_t*)Vh[kt & 1];

        // S = Q K^T  (fp16 m16n8k16; B-frag: b0=K[key=8j+g][d 16t+2m..], b1=+8)
        float S[8][4];
#pragma unroll
        for (int j = 0; j < 8; j++) {
            S[j][0] = S[j][1] = S[j][2] = S[j][3] = 0.f;
#pragma unroll
            for (int t = 0; t < 4; t++) {
                uint32_t bf[2];
                bf[0] = Kw[(j * 8 + g) * 36 + 8 * t + m];
                bf[1] = Kw[(j * 8 + g) * 36 + 8 * t + m + 4];
                mma_f16(S[j], Aq[t], bf);
            }
        }

        // Online softmax (log2 domain); P as fp16 fragments in registers
        float tlo = -1e30f, thi = -1e30f;
#pragma unroll
        for (int j = 0; j < 8; j++) {
            tlo = fmaxf(tlo, fmaxf(S[j][0], S[j][1]));
            thi = fmaxf(thi, fmaxf(S[j][2], S[j][3]));
        }
#pragma unroll
        for (int o = 1; o <= 2; o <<= 1) {
            tlo = fmaxf(tlo, __shfl_xor_sync(0xffffffffu, tlo, o));
            thi = fmaxf(thi, __shfl_xor_sync(0xffffffffu, thi, o));
        }
        float nlo = fmaxf(mlo, tlo), nhi = fmaxf(mhi, thi);
        float clo = ex2f(mlo - nlo), chi = ex2f(mhi - nhi);
        mlo = nlo; mhi = nhi;
        float ssl = 0.f, ssh = 0.f;
        uint32_t Pf[8][2];
#pragma unroll
        for (int j = 0; j < 8; j++) {
            float p0 = ex2f(S[j][0] - nlo);
            float p1 = ex2f(S[j][1] - nlo);
            float p2 = ex2f(S[j][2] - nhi);
            float p3 = ex2f(S[j][3] - nhi);
            ssl += p0 + p1; ssh += p2 + p3;
            O[j][0] *= clo; O[j][1] *= clo; O[j][2] *= chi; O[j][3] *= chi;
            Pf[j][0] = f16x2(p0, p1);
            Pf[j][1] = f16x2(p2, p3);
        }
#pragma unroll
        for (int o = 1; o <= 2; o <<= 1) {
            ssl += __shfl_xor_sync(0xffffffffu, ssl, o);
            ssh += __shfl_xor_sync(0xffffffffu, ssh, o);
        }
        slo = slo * clo + ssl;
        shi = shi * chi + ssh;

        // O += P @ V  (fp16 m16n8k16, register-relay P; B-frag from V[d][keypair])
#pragma unroll
        for (int t = 0; t < 4; t++) {
            uint32_t Ap[4];
            Ap[0] = Pf[2 * t][0];
            Ap[1] = Pf[2 * t][1];
            Ap[2] = Pf[2 * t + 1][0];
            Ap[3] = Pf[2 * t + 1][1];
#pragma unroll
            for (int j = 0; j < 8; j++) {
                uint32_t bf[2];
                bf[0] = Vw[(j * 8 + g) * 36 + 8 * t + m];
                bf[1] = Vw[(j * 8 + g) * 36 + 8 * t + m + 4];
                mma_f16(O[j], Ap, bf);
            }
        }
        __syncthreads();    // all reads of this stage done before it is refilled
    }

    // Epilogue: normalize, write c-major for proj GEMM
    float* aob = g_ao + ((size_t)b * C_ + h * HD_) * N_;
    float ilo = 1.f / slo, ihi = 1.f / shi;
#pragma unroll
    for (int j = 0; j < 8; j++) {
        int d = j * 8 + 2 * m;
        aob[(size_t)d * N_ + qlo]       = O[j][0] * ilo;
        aob[(size_t)(d + 1) * N_ + qlo] = O[j][1] * ilo;
        aob[(size_t)d * N_ + qhi]       = O[j][2] * ihi;
        aob[(size_t)(d + 1) * N_ + qhi] = O[j][3] * ihi;
    }
}

// ---------------------------------------------------------------------------
// Launch sequence
// ---------------------------------------------------------------------------
extern "C" void kernel_launch(void* const* d_in, const int* in_sizes, int n_in,
                              void* d_out, int out_size) {
    const float* x    = (const float*)d_in[0];
    const float* gw   = (const float*)d_in[1];
    const float* gb   = (const float*)d_in[2];
    const float* qkvw = (const float*)d_in[3];
    const float* qkvb = (const float*)d_in[4];
    const float* pw   = (const float*)d_in[5];
    const float* pb   = (const float*)d_in[6];
    float* out = (float*)d_out;

    float *hn, *qkv, *ao;
    cudaGetSymbolAddress((void**)&hn,  g_hn);
    cudaGetSymbolAddress((void**)&qkv, g_qkv);
    cudaGetSymbolAddress((void**)&ao,  g_ao);

    gn_stats_k<<<B_ * NG_, 256>>>(x);
    gn_apply_k<<<(B_ * C_ * N_ / 4) / 256, 256>>>(x, gw, gb);
    {
        dim3 g(N_ / 64, (3 * C_) / 64, B_);
        sgemm_tc<<<g, 128>>>(qkvw, hn, qkvb, nullptr, qkv, 3 * C_, C_);
    }
    {
        dim3 g(N_ / 64, B_ * NH_);
        repack_kv_k<<<g, 256>>>();
    }
    {
        dim3 g(N_ / 64, NH_, B_);
        attn_k<<<g, 128>>>();
    }
    {
        dim3 g(N_ / 64, C_ / 64, B_);
        sgemm_tc<<<g, 128>>>(pw, ao, pb, x, out, C_, C_);
    }
}

// round 8
// speedup vs baseline: 6.6479x; 1.1051x over previous
#include <cuda_runtime.h>
#include <cuda_fp16.h>
#include <cstdint>

// Problem constants
#define B_   4
#define C_   256
#define N_   4096          // H*W = 64*64
#define NH_  4
#define HD_  64
#define NG_  8
#define CPG_ 32
#define EPS_ 1e-5f
#define SCALE_ 0.125f      // HD^-0.5
#define LOG2E_ 1.4426950408889634f

// Scratch
__device__ uint16_t g_hnt [(size_t)B_ * N_ * C_];       // GN output, fp16 [b][n][c]
__device__ uint16_t g_qkvh[(size_t)B_ * 3 * C_ * N_];   // QKV fp16 [b][3C][n]
__device__ uint16_t g_kt  [(size_t)B_ * NH_ * N_ * HD_];// K fp16 key-major [bh][key][d]
__device__ uint16_t g_aot [(size_t)B_ * N_ * C_];       // attn out fp16 [b][n][c]
__device__ uint16_t g_w16 [(3 * C_ + C_) * C_];         // qkv_w + proj_w fp16
__device__ float    g_stats[B_ * NG_ * 2];

// ---------------------------------------------------------------------------
// helpers
// ---------------------------------------------------------------------------
__device__ __forceinline__ float ex2f(float x) {
    float y;
    asm("ex2.approx.ftz.f32 %0, %1;" : "=f"(y) : "f"(x));
    return y;
}
__device__ __forceinline__ uint32_t f16x2(float a, float b) {   // {lo:a, hi:b}
    uint32_t r;
    asm("cvt.rn.f16x2.f32 %0, %1, %2;" : "=r"(r) : "f"(b), "f"(a));
    return r;
}
__device__ __forceinline__ uint32_t smem_u32(const void* p) {
    uint32_t a;
    asm("{ .reg .u64 t; cvta.to.shared.u64 t, %1; cvt.u32.u64 %0, t; }" : "=r"(a) : "l"(p));
    return a;
}
__device__ __forceinline__ void cpa16(uint32_t s, const void* g) {
    asm volatile("cp.async.cg.shared.global [%0], [%1], 16;" :: "r"(s), "l"(g));
}
__device__ __forceinline__ void cpa_commit() { asm volatile("cp.async.commit_group;"); }
__device__ __forceinline__ void cpa_wait1()  { asm volatile("cp.async.wait_group 1;"); }
__device__ __forceinline__ void cpa_wait0()  { asm volatile("cp.async.wait_group 0;"); }

__device__ __forceinline__ void mma_f16(float* d, const uint32_t* a, const uint32_t* b) {
    asm("mma.sync.aligned.m16n8k16.row.col.f32.f16.f16.f32 "
        "{%0,%1,%2,%3}, {%4,%5,%6,%7}, {%8,%9}, {%0,%1,%2,%3};"
        : "+f"(d[0]), "+f"(d[1]), "+f"(d[2]), "+f"(d[3])
        : "r"(a[0]), "r"(a[1]), "r"(a[2]), "r"(a[3]), "r"(b[0]), "r"(b[1]));
}

// ---------------------------------------------------------------------------
// GroupNorm statistics
// ---------------------------------------------------------------------------
__global__ void gn_stats_k(const float* __restrict__ x) {
    int bg = blockIdx.x;
    const float4* base = (const float4*)(x + (size_t)bg * CPG_ * N_);
    int tid = threadIdx.x;
    float s = 0.f, s2 = 0.f;
    const int nv = CPG_ * N_ / 4;
    for (int i = tid; i < nv; i += 256) {
        float4 v = base[i];
        s  += v.x + v.y + v.z + v.w;
        s2 += v.x * v.x + v.y * v.y + v.z * v.z + v.w * v.w;
    }
    __shared__ float rs[256], rq[256];
    rs[tid] = s; rq[tid] = s2;
    __syncthreads();
    for (int o = 128; o > 0; o >>= 1) {
        if (tid < o) { rs[tid] += rs[tid + o]; rq[tid] += rq[tid + o]; }
        __syncthreads();
    }
    if (tid == 0) {
        const float invn = 1.f / (float)(CPG_ * N_);
        float mean = rs[0] * invn;
        float var  = rq[0] * invn - mean * mean;
        g_stats[bg * 2 + 0] = mean;
        g_stats[bg * 2 + 1] = rsqrtf(var + EPS_);
    }
}

// ---------------------------------------------------------------------------
// GroupNorm apply + transpose: x[b][c][n] fp32 -> g_hnt[b][n][c] fp16.
// Grid (N/64, C/64, B), 256 threads; 64c x 64n tile through smem.
// ---------------------------------------------------------------------------
__global__ void gn_t_k(const float* __restrict__ x,
                       const float* __restrict__ gw,
                       const float* __restrict__ gb) {
    int n0 = blockIdx.x * 64, c0 = blockIdx.y * 64, b = blockIdx.z;
    int t = threadIdx.x;

    __shared__ __half ht[64][72];   // [c_local][n_local]

    int n_l = t & 63, cq = t >> 6;                  // cq = 0..3
#pragma unroll
    for (int it = 0; it < 16; it++) {
        int c_l = it * 4 + cq;
        int c = c0 + c_l;
        int bg = b * NG_ + (c >> 5);
        float mean = g_stats[bg * 2 + 0];
        float rstd = g_stats[bg * 2 + 1];
        float ga = gw[c] * rstd;
        float be = gb[c] - mean * ga;
        float v = x[((size_t)b * C_ + c) * N_ + n0 + n_l];
        ht[c_l][n_l] = __float2half(v * ga + be);
    }
    __syncthreads();

    // write rows [n][c]: thread = (n = t>>2, chunk = t&3 covering 16 c)
    int n_o = t >> 2, ch = t & 3;
    uint32_t pk[8];
#pragma unroll
    for (int u = 0; u < 8; u++) {
        __half2 h2 = __halves2half2(ht[ch * 16 + 2 * u][n_o], ht[ch * 16 + 2 * u + 1][n_o]);
        pk[u] = *(uint32_t*)&h2;
    }
    uint16_t* orow = g_hnt + ((size_t)b * N_ + n0 + n_o) * C_ + c0 + ch * 16;
    *(uint4*)(orow)     = *(uint4*)&pk[0];
    *(uint4*)(orow + 8) = *(uint4*)&pk[4];
}

// ---------------------------------------------------------------------------
// Weight pack fp32 -> fp16 (qkv_w then proj_w)
// ---------------------------------------------------------------------------
__global__ void w2h_k(const float* __restrict__ w, int n4, int off) {
    int i = blockIdx.x * 256 + threadIdx.x;
    if (i >= n4) return;
    float4 v = ((const float4*)w)[i];
    uint2 o;
    o.x = f16x2(v.x, v.y);
    o.y = f16x2(v.z, v.w);
    *(uint2*)(g_w16 + off + (size_t)i * 4) = o;
}

// ---------------------------------------------------------------------------
// fp16 tensor-core GEMM: Out[b][m][n] = sum_k W16[m][k] * Bt[b][n][k] + bias
// CTA 64m x 64n, 128 threads, warp = 16m x 64n, K=256 fixed, slab k32.
// Bt is n-major fp16 (stride C_); Bs smem [64n][72hw] -> conflict-free frags.
// Output fp16 [m][n] (outh) OR fp32 + residual (outf).
// ---------------------------------------------------------------------------
__global__ __launch_bounds__(128) void hgemm_k(const uint16_t* __restrict__ W16,
                                               const uint16_t* __restrict__ Bt,
                                               const float* __restrict__ bias,
                                               const float* __restrict__ res,
                                               uint16_t* __restrict__ outh,
                                               float* __restrict__ outf,
                                               int M) {
    const int K = C_;
    int b  = blockIdx.z;
    const uint16_t* Btb = Bt + (size_t)b * N_ * K;
    int m0 = blockIdx.y * 64, n0 = blockIdx.x * 64;

    __shared__ uint16_t Bs[2][64 * 72];
    uint32_t bsm[2] = { smem_u32(Bs[0]), smem_u32(Bs[1]) };

    int tid = threadIdx.x, w = tid >> 5, lane = tid & 31;
    int g = lane >> 2, m = lane & 3;
    int r_lo = m0 + w * 16 + g, r_hi = r_lo + 8;

    float acc[8][4];
#pragma unroll
    for (int j = 0; j < 8; j++)
#pragma unroll
        for (int i = 0; i < 4; i++) acc[j][i] = 0.f;

    const int NS = K / 32;   // 8 slabs
    // prologue: slab 0 (64 rows x 64B)
    {
#pragma unroll
        for (int it = 0; it < 2; it++) {
            int idx = it * 128 + tid;
            int r = idx >> 2, c = idx & 3;
            cpa16(bsm[0] + (uint32_t)(r * 144 + c * 16),
                  Btb + (size_t)(n0 + r) * K + c * 8);
        }
        cpa_commit();
    }
    for (int ks = 0; ks < NS; ks++) {
        if (ks + 1 < NS) {
            int s = (ks + 1) & 1, k0 = (ks + 1) * 32;
#pragma unroll
            for (int it = 0; it < 2; it++) {
                int idx = it * 128 + tid;
                int r = idx >> 2, c = idx & 3;
                cpa16(bsm[s] + (uint32_t)(r * 144 + c * 16),
                      Btb + (size_t)(n0 + r) * K + k0 + c * 8);
            }
            cpa_commit();
            cpa_wait1();
        } else {
            cpa_wait0();
        }
        __syncthreads();
        const uint32_t* Bc = (const uint32_t*)Bs[ks & 1];
        int k0 = ks * 32;
#pragma unroll
        for (int t = 0; t < 2; t++) {
            int kk = k0 + t * 16 + 2 * m;
            uint32_t a[4];
            a[0] = *(const uint32_t*)&W16[(size_t)r_lo * K + kk];
            a[1] = *(const uint32_t*)&W16[(size_t)r_hi * K + kk];
            a[2] = *(const uint32_t*)&W16[(size_t)r_lo * K + kk + 8];
            a[3] = *(const uint32_t*)&W16[(size_t)r_hi * K + kk + 8];
#pragma unroll
            for (int j = 0; j < 8; j++) {
                uint32_t bb[2];
                bb[0] = Bc[(j * 8 + g) * 36 + 8 * t + m];
                bb[1] = Bc[(j * 8 + g) * 36 + 8 * t + m + 4];
                mma_f16(acc[j], a, bb);
            }
        }
        __syncthreads();
    }

    float b_lo = bias[r_lo], b_hi = bias[r_hi];
    if (outh) {
        uint16_t* Ob = outh + (size_t)b * M * N_;
#pragma unroll
        for (int j = 0; j < 8; j++) {
            int n = n0 + j * 8 + 2 * m;
            *(uint32_t*)&Ob[(size_t)r_lo * N_ + n] = f16x2(acc[j][0] + b_lo, acc[j][1] + b_lo);
            *(uint32_t*)&Ob[(size_t)r_hi * N_ + n] = f16x2(acc[j][2] + b_hi, acc[j][3] + b_hi);
        }
    } else {
        float* Ob = outf + (size_t)b * M * N_;
        const float* resb = res + (size_t)b * M * N_;
#pragma unroll
        for (int j = 0; j < 8; j++) {
            int n = n0 + j * 8 + 2 * m;
            size_t olo = (size_t)r_lo * N_ + n;
            size_t ohi = (size_t)r_hi * N_ + n;
            float2 rl = *(const float2*)&resb[olo];
            float2 rh = *(const float2*)&resb[ohi];
            float2 vlo; vlo.x = acc[j][0] + b_lo + rl.x; vlo.y = acc[j][1] + b_lo + rl.y;
            float2 vhi; vhi.x = acc[j][2] + b_hi + rh.x; vhi.y = acc[j][3] + b_hi + rh.y;
            *(float2*)&Ob[olo] = vlo;
            *(float2*)&Ob[ohi] = vhi;
        }
    }
}

// ---------------------------------------------------------------------------
// Repack K: fp16 [d][n] -> key-major fp16 [bh][key][64]
// ---------------------------------------------------------------------------
__global__ void repack_k_k() {
    int bh = blockIdx.y;
    int b = bh >> 2, h = bh & 3;
    const uint16_t* kb = g_qkvh + ((size_t)b * 3 * C_ + C_ + h * HD_) * N_;
    int key0 = blockIdx.x * 64;
    int t = threadIdx.x;

    __shared__ uint16_t kt[64][65];

    int key = t & 63, dg = t >> 6;
#pragma unroll
    for (int i = 0; i < 16; i++) {
        int d = dg * 16 + i;
        kt[d][key] = kb[(size_t)d * N_ + key0 + key];
    }
    __syncthreads();

    int okey = t >> 2, c = t & 3;
    uint32_t pk[8];
#pragma unroll
    for (int u = 0; u < 8; u++) {
        pk[u] = (uint32_t)kt[c * 16 + 2 * u][okey] | ((uint32_t)kt[c * 16 + 2 * u + 1][okey] << 16);
    }
    uint16_t* orow = g_kt + ((size_t)bh * N_ + key0 + okey) * HD_ + c * 16;
    *(uint4*)(orow)     = *(uint4*)&pk[0];
    *(uint4*)(orow + 8) = *(uint4*)&pk[4];
}

// ---------------------------------------------------------------------------
// Flash attention (fp16 MMA, as R7) — Q/V read fp16 from g_qkvh, K from g_kt,
// epilogue writes fp16 ao_t [b][n][c] (the proj GEMM's B operand).
// ---------------------------------------------------------------------------
__global__ __launch_bounds__(128, 4) void attn_k() {
    int qt = blockIdx.x, h = blockIdx.y, b = blockIdx.z;
    int bh = b * NH_ + h;
    const uint16_t* qb  = g_qkvh + ((size_t)b * 3 * C_ + h * HD_) * N_;
    const uint16_t* khb = g_kt + (size_t)bh * N_ * HD_;
    const uint16_t* vhb = g_qkvh + ((size_t)b * 3 * C_ + 2 * C_ + h * HD_) * N_;

    __shared__ uint16_t Kh[2][64 * 72];
    __shared__ uint16_t Vh[2][64 * 72];
    uint32_t ksm[2] = { smem_u32(Kh[0]), smem_u32(Kh[1]) };
    uint32_t vsm[2] = { smem_u32(Vh[0]), smem_u32(Vh[1]) };

    int tid = threadIdx.x, w = tid >> 5, lane = tid & 31;
    int g = lane >> 2, m = lane & 3;
    int q0 = qt * 64;

    // prologue: tile 0 into stage 0
    {
#pragma unroll
        for (int it = 0; it < 4; it++) {
            int idx = it * 128 + tid;
            int r = idx >> 3, c = idx & 7;
            cpa16(ksm[0] + (uint32_t)(r * 144 + c * 16), khb + (size_t)r * HD_ + c * 8);
        }
#pragma unroll
        for (int it = 0; it < 4; it++) {
            int idx = it * 128 + tid;
            int r = idx >> 3, c = idx & 7;
            cpa16(vsm[0] + (uint32_t)(r * 144 + c * 16), vhb + (size_t)r * N_ + c * 8);
        }
        cpa_commit();
    }

    // Q A-fragments (fp16), scaled for log2-domain softmax
    const float qs = SCALE_ * LOG2E_;
    uint32_t Aq[4][4];
    int qlo = q0 + w * 16 + g, qhi = qlo + 8;
#pragma unroll
    for (int t = 0; t < 4; t++) {
        int d0 = t * 16 + 2 * m;
#pragma unroll
        for (int hseg = 0; hseg < 2; hseg++) {
            int d = d0 + hseg * 8;
            float a0 = __half2float(__ushort_as_half(qb[(size_t)d * N_ + qlo])) * qs;
            float a1 = __half2float(__ushort_as_half(qb[(size_t)(d + 1) * N_ + qlo])) * qs;
            float a2 = __half2float(__ushort_as_half(qb[(size_t)d * N_ + qhi])) * qs;
            float a3 = __half2float(__ushort_as_half(qb[(size_t)(d + 1) * N_ + qhi])) * qs;
            Aq[t][2 * hseg]     = f16x2(a0, a1);
            Aq[t][2 * hseg + 1] = f16x2(a2, a3);
        }
    }

    float O[8][4];
#pragma unroll
    for (int j = 0; j < 8; j++)
#pragma unroll
        for (int i = 0; i < 4; i++) O[j][i] = 0.f;
    float mlo = -1e30f, mhi = -1e30f, slo = 0.f, shi = 0.f;

    const int NT = N_ / 64;
    for (int kt = 0; kt < NT; kt++) {
        if (kt + 1 < NT) {
            int s = (kt + 1) & 1, k0t = (kt + 1) * 64;
#pragma unroll
            for (int it = 0; it < 4; it++) {
                int idx = it * 128 + tid;
                int r = idx >> 3, c = idx & 7;
                cpa16(ksm[s] + (uint32_t)(r * 144 + c * 16),
                      khb + (size_t)(k0t + r) * HD_ + c * 8);
            }
#pragma unroll
            for (int it = 0; it < 4; it++) {
                int idx = it * 128 + tid;
                int r = idx >> 3, c = idx & 7;
                cpa16(vsm[s] + (uint32_t)(r * 144 + c * 16),
                      vhb + (size_t)r * N_ + k0t + c * 8);
            }
            cpa_commit();
            cpa_wait1();
        } else {
            cpa_wait0();
        }
        __syncthreads();

        const uint32_t* Kw = (const uint32_t*)Kh[kt & 1];
        const uint32_t* Vw = (const uint32_t*)Vh[kt & 1];

        // S = Q K^T
        float S[8][4];
#pragma unroll
        for (int j = 0; j < 8; j++) {
            S[j][0] = S[j][1] = S[j][2] = S[j][3] = 0.f;
#pragma unroll
            for (int t = 0; t < 4; t++) {
                uint32_t bf[2];
                bf[0] = Kw[(j * 8 + g) * 36 + 8 * t + m];
                bf[1] = Kw[(j * 8 + g) * 36 + 8 * t + m + 4];
                mma_f16(S[j], Aq[t], bf);
            }
        }

        // Online softmax (log2 domain)
        float tlo = -1e30f, thi = -1e30f;
#pragma unroll
        for (int j = 0; j < 8; j++) {
            tlo = fmaxf(tlo, fmaxf(S[j][0], S[j][1]));
            thi = fmaxf(thi, fmaxf(S[j][2], S[j][3]));
        }
#pragma unroll
        for (int o = 1; o <= 2; o <<= 1) {
            tlo = fmaxf(tlo, __shfl_xor_sync(0xffffffffu, tlo, o));
            thi = fmaxf(thi, __shfl_xor_sync(0xffffffffu, thi, o));
        }
        float nlo = fmaxf(mlo, tlo), nhi = fmaxf(mhi, thi);
        float clo = ex2f(mlo - nlo), chi = ex2f(mhi - nhi);
        mlo = nlo; mhi = nhi;
        float ssl = 0.f, ssh = 0.f;
        uint32_t Pf[8][2];
#pragma unroll
        for (int j = 0; j < 8; j++) {
            float p0 = ex2f(S[j][0] - nlo);
            float p1 = ex2f(S[j][1] - nlo);
            float p2 = ex2f(S[j][2] - nhi);
            float p3 = ex2f(S[j][3] - nhi);
            ssl += p0 + p1; ssh += p2 + p3;
            O[j][0] *= clo; O[j][1] *= clo; O[j][2] *= chi; O[j][3] *= chi;
            Pf[j][0] = f16x2(p0, p1);
            Pf[j][1] = f16x2(p2, p3);
        }
#pragma unroll
        for (int o = 1; o <= 2; o <<= 1) {
            ssl += __shfl_xor_sync(0xffffffffu, ssl, o);
            ssh += __shfl_xor_sync(0xffffffffu, ssh, o);
        }
        slo = slo * clo + ssl;
        shi = shi * chi + ssh;

        // O += P @ V  (register-relay P)
#pragma unroll
        for (int t = 0; t < 4; t++) {
            uint32_t Ap[4];
            Ap[0] = Pf[2 * t][0];
            Ap[1] = Pf[2 * t][1];
            Ap[2] = Pf[2 * t + 1][0];
            Ap[3] = Pf[2 * t + 1][1];
#pragma unroll
            for (int j = 0; j < 8; j++) {
                uint32_t bf[2];
                bf[0] = Vw[(j * 8 + g) * 36 + 8 * t + m];
                bf[1] = Vw[(j * 8 + g) * 36 + 8 * t + m + 4];
                mma_f16(O[j], Ap, bf);
            }
        }
        __syncthreads();
    }

    // Epilogue: normalize, write fp16 ao_t[b][q][c] (proj GEMM B operand)
    uint16_t* aob = g_aot + ((size_t)b * N_) * C_ + h * HD_;
    float ilo = 1.f / slo, ihi = 1.f / shi;
#pragma unroll
    for (int j = 0; j < 8; j++) {
        int d = j * 8 + 2 * m;
        *(uint32_t*)&aob[(size_t)qlo * C_ + d] = f16x2(O[j][0] * ilo, O[j][1] * ilo);
        *(uint32_t*)&aob[(size_t)qhi * C_ + d] = f16x2(O[j][2] * ihi, O[j][3] * ihi);
    }
}

// ---------------------------------------------------------------------------
// Launch sequence
// ---------------------------------------------------------------------------
extern "C" void kernel_launch(void* const* d_in, const int* in_sizes, int n_in,
                              void* d_out, int out_size) {
    const float* x    = (const float*)d_in[0];
    const float* gw   = (const float*)d_in[1];
    const float* gb   = (const float*)d_in[2];
    const float* qkvw = (const float*)d_in[3];
    const float* qkvb = (const float*)d_in[4];
    const float* pw   = (const float*)d_in[5];
    const float* pb   = (const float*)d_in[6];
    float* out = (float*)d_out;

    uint16_t *hnt, *qkvh, *aot, *w16;
    cudaGetSymbolAddress((void**)&hnt,  g_hnt);
    cudaGetSymbolAddress((void**)&qkvh, g_qkvh);
    cudaGetSymbolAddress((void**)&aot,  g_aot);
    cudaGetSymbolAddress((void**)&w16,  g_w16);

    // 1) GroupNorm stats
    gn_stats_k<<<B_ * NG_, 256>>>(x);
    // 2) Weight packs (independent of stats)
    w2h_k<<<(3 * C_ * C_ / 4 + 255) / 256, 256>>>(qkvw, 3 * C_ * C_ / 4, 0);
    w2h_k<<<(C_ * C_ / 4 + 255) / 256, 256>>>(pw, C_ * C_ / 4, 3 * C_ * C_);
    // 3) GN apply + transpose -> hnt fp16 [b][n][c]
    {
        dim3 g(N_ / 64, C_ / 64, B_);
        gn_t_k<<<g, 256>>>(x, gw, gb);
    }
    // 4) QKV fp16 GEMM -> qkvh fp16 [b][3C][n]
    {
        dim3 g(N_ / 64, (3 * C_) / 64, B_);
        hgemm_k<<<g, 128>>>(w16, hnt, qkvb, nullptr, qkvh, nullptr, 3 * C_);
    }
    // 5) K transpose
    {
        dim3 g(N_ / 64, B_ * NH_);
        repack_k_k<<<g, 256>>>();
    }
    // 6) Flash attention -> aot fp16 [b][n][c]
    {
        dim3 g(N_ / 64, NH_, B_);
        attn_k<<<g, 128>>>();
    }
    // 7) proj fp16 GEMM + bias + residual -> d_out fp32
    {
        dim3 g(N_ / 64, C_ / 64, B_);
        hgemm_k<<<g, 128>>>(w16 + 3 * C_ * C_, aot, pb, x, nullptr, out, C_);
    }
}

// round 9
// speedup vs baseline: 7.0041x; 1.0536x over previous
#include <cuda_runtime.h>
#include <cuda_fp16.h>
#include <cstdint>

// Problem constants
#define B_   4
#define C_   256
#define N_   4096          // H*W = 64*64
#define NH_  4
#define HD_  64
#define NG_  8
#define CPG_ 32
#define EPS_ 1e-5f
#define SCALE_ 0.125f      // HD^-0.5
#define LOG2E_ 1.4426950408889634f

// Scratch
__device__ uint16_t g_hnt [(size_t)B_ * N_ * C_];       // GN output, fp16 [b][n][c]
__device__ uint16_t g_qkvh[(size_t)B_ * 3 * C_ * N_];   // QKV fp16 [b][3C][n]
__device__ uint16_t g_kt  [(size_t)B_ * NH_ * N_ * HD_];// K fp16 key-major [bh][key][d]
__device__ uint16_t g_aot [(size_t)B_ * N_ * C_];       // attn out fp16 [b][n][c]
__device__ uint16_t g_w16 [(3 * C_ + C_) * C_];         // qkv_w + proj_w fp16
__device__ float    g_part[256 * 2];                    // partial GN sums
__device__ float    g_stats[B_ * NG_ * 2];

// ---------------------------------------------------------------------------
// helpers
// ---------------------------------------------------------------------------
__device__ __forceinline__ float ex2f(float x) {
    float y;
    asm("ex2.approx.ftz.f32 %0, %1;" : "=f"(y) : "f"(x));
    return y;
}
__device__ __forceinline__ uint32_t f16x2(float a, float b) {   // {lo:a, hi:b}
    uint32_t r;
    asm("cvt.rn.f16x2.f32 %0, %1, %2;" : "=r"(r) : "f"(b), "f"(a));
    return r;
}
__device__ __forceinline__ uint32_t smem_u32(const void* p) {
    uint32_t a;
    asm("{ .reg .u64 t; cvta.to.shared.u64 t, %1; cvt.u32.u64 %0, t; }" : "=r"(a) : "l"(p));
    return a;
}
__device__ __forceinline__ void cpa16(uint32_t s, const void* g) {
    asm volatile("cp.async.cg.shared.global [%0], [%1], 16;" :: "r"(s), "l"(g));
}
__device__ __forceinline__ void cpa_commit() { asm volatile("cp.async.commit_group;"); }
__device__ __forceinline__ void cpa_wait2()  { asm volatile("cp.async.wait_group 2;"); }
__device__ __forceinline__ void cpa_wait1()  { asm volatile("cp.async.wait_group 1;"); }
__device__ __forceinline__ void cpa_wait0()  { asm volatile("cp.async.wait_group 0;"); }

__device__ __forceinline__ void ldsm4(uint32_t& r0, uint32_t& r1, uint32_t& r2, uint32_t& r3,
                                      uint32_t a) {
    asm volatile("ldmatrix.sync.aligned.m8n8.x4.shared.b16 {%0,%1,%2,%3}, [%4];"
                 : "=r"(r0), "=r"(r1), "=r"(r2), "=r"(r3) : "r"(a));
}
__device__ __forceinline__ void mma_f16(float* d, const uint32_t* a, const uint32_t* b) {
    asm("mma.sync.aligned.m16n8k16.row.col.f32.f16.f16.f32 "
        "{%0,%1,%2,%3}, {%4,%5,%6,%7}, {%8,%9}, {%0,%1,%2,%3};"
        : "+f"(d[0]), "+f"(d[1]), "+f"(d[2]), "+f"(d[3])
        : "r"(a[0]), "r"(a[1]), "r"(a[2]), "r"(a[3]), "r"(b[0]), "r"(b[1]));
}

// ---------------------------------------------------------------------------
// GroupNorm statistics, phase 1: 256 blocks, 8 partials per (b,g)
// ---------------------------------------------------------------------------
__global__ void gn_stats1_k(const float* __restrict__ x) {
    int blk = blockIdx.x;               // bg = blk>>3, part = blk&7
    int bg = blk >> 3, part = blk & 7;
    const float4* base = (const float4*)(x + (size_t)bg * CPG_ * N_) + part * 4096;
    int tid = threadIdx.x;
    float s = 0.f, s2 = 0.f;
    for (int i = tid; i < 4096; i += 256) {
        float4 v = base[i];
        s  += v.x + v.y + v.z + v.w;
        s2 += v.x * v.x + v.y * v.y + v.z * v.z + v.w * v.w;
    }
    __shared__ float rs[256], rq[256];
    rs[tid] = s; rq[tid] = s2;
    __syncthreads();
    for (int o = 128; o > 0; o >>= 1) {
        if (tid < o) { rs[tid] += rs[tid + o]; rq[tid] += rq[tid + o]; }
        __syncthreads();
    }
    if (tid == 0) {
        g_part[blk * 2 + 0] = rs[0];
        g_part[blk * 2 + 1] = rq[0];
    }
}

// phase 2: one tiny block reduces 8 partials per (b,g)
__global__ void gn_stats2_k() {
    int t = threadIdx.x;
    if (t < B_ * NG_) {
        float s = 0.f, s2 = 0.f;
#pragma unroll
        for (int p = 0; p < 8; p++) {
            s  += g_part[(t * 8 + p) * 2 + 0];
            s2 += g_part[(t * 8 + p) * 2 + 1];
        }
        const float invn = 1.f / (float)(CPG_ * N_);
        float mean = s * invn;
        float var  = s2 * invn - mean * mean;
        g_stats[t * 2 + 0] = mean;
        g_stats[t * 2 + 1] = rsqrtf(var + EPS_);
    }
}

// ---------------------------------------------------------------------------
// GroupNorm apply + transpose: x[b][c][n] fp32 -> g_hnt[b][n][c] fp16.
// ---------------------------------------------------------------------------
__global__ void gn_t_k(const float* __restrict__ x,
                       const float* __restrict__ gw,
                       const float* __restrict__ gb) {
    int n0 = blockIdx.x * 64, c0 = blockIdx.y * 64, b = blockIdx.z;
    int t = threadIdx.x;

    __shared__ __half ht[64][72];   // [c_local][n_local]

    int n_l = t & 63, cq = t >> 6;
#pragma unroll
    for (int it = 0; it < 16; it++) {
        int c_l = it * 4 + cq;
        int c = c0 + c_l;
        int bg = b * NG_ + (c >> 5);
        float mean = g_stats[bg * 2 + 0];
        float rstd = g_stats[bg * 2 + 1];
        float ga = gw[c] * rstd;
        float be = gb[c] - mean * ga;
        float v = x[((size_t)b * C_ + c) * N_ + n0 + n_l];
        ht[c_l][n_l] = __float2half(v * ga + be);
    }
    __syncthreads();

    int n_o = t >> 2, ch = t & 3;
    uint32_t pk[8];
#pragma unroll
    for (int u = 0; u < 8; u++) {
        __half2 h2 = __halves2half2(ht[ch * 16 + 2 * u][n_o], ht[ch * 16 + 2 * u + 1][n_o]);
        pk[u] = *(uint32_t*)&h2;
    }
    uint16_t* orow = g_hnt + ((size_t)b * N_ + n0 + n_o) * C_ + c0 + ch * 16;
    *(uint4*)(orow)     = *(uint4*)&pk[0];
    *(uint4*)(orow + 8) = *(uint4*)&pk[4];
}

// ---------------------------------------------------------------------------
// Weight pack fp32 -> fp16
// ---------------------------------------------------------------------------
__global__ void w2h_k(const float* __restrict__ w, int n4, int off) {
    int i = blockIdx.x * 256 + threadIdx.x;
    if (i >= n4) return;
    float4 v = ((const float4*)w)[i];
    uint2 o;
    o.x = f16x2(v.x, v.y);
    o.y = f16x2(v.z, v.w);
    *(uint2*)(g_w16 + off + (size_t)i * 4) = o;
}

// ---------------------------------------------------------------------------
// fp16 tensor-core GEMM (ldmatrix B-frags): Out = W16 @ Bt^T + bias
// CTA 64m x 64n, 128 threads, K=256, slab k32.
// ---------------------------------------------------------------------------
__global__ __launch_bounds__(128) void hgemm_k(const uint16_t* __restrict__ W16,
                                               const uint16_t* __restrict__ Bt,
                                               const float* __restrict__ bias,
                                               const float* __restrict__ res,
                                               uint16_t* __restrict__ outh,
                                               float* __restrict__ outf,
                                               int M) {
    const int K = C_;
    int b  = blockIdx.z;
    const uint16_t* Btb = Bt + (size_t)b * N_ * K;
    int m0 = blockIdx.y * 64, n0 = blockIdx.x * 64;

    __shared__ uint16_t Bs[2][64 * 72];
    uint32_t bsm[2] = { smem_u32(Bs[0]), smem_u32(Bs[1]) };

    int tid = threadIdx.x, w = tid >> 5, lane = tid & 31;
    int g = lane >> 2, m = lane & 3;
    int r_lo = m0 + w * 16 + g, r_hi = r_lo + 8;
    uint32_t lmrow = (uint32_t)((lane & 7) * 144 + (lane >> 3) * 16);

    float acc[8][4];
#pragma unroll
    for (int j = 0; j < 8; j++)
#pragma unroll
        for (int i = 0; i < 4; i++) acc[j][i] = 0.f;

    const int NS = K / 32;   // 8 slabs
    {
#pragma unroll
        for (int it = 0; it < 2; it++) {
            int idx = it * 128 + tid;
            int r = idx >> 2, c = idx & 3;
            cpa16(bsm[0] + (uint32_t)(r * 144 + c * 16),
                  Btb + (size_t)(n0 + r) * K + c * 8);
        }
        cpa_commit();
    }
    for (int ks = 0; ks < NS; ks++) {
        if (ks + 1 < NS) {
            int s = (ks + 1) & 1, k0 = (ks + 1) * 32;
#pragma unroll
            for (int it = 0; it < 2; it++) {
                int idx = it * 128 + tid;
                int r = idx >> 2, c = idx & 3;
                cpa16(bsm[s] + (uint32_t)(r * 144 + c * 16),
                      Btb + (size_t)(n0 + r) * K + k0 + c * 8);
            }
            cpa_commit();
            cpa_wait1();
        } else {
            cpa_wait0();
        }
        __syncthreads();
        int k0 = ks * 32;
        // A-frags for the 2 k16 chunks of this slab
        uint32_t a0[4], a1[4];
        {
            int kk = k0 + 2 * m;
            a0[0] = *(const uint32_t*)&W16[(size_t)r_lo * K + kk];
            a0[1] = *(const uint32_t*)&W16[(size_t)r_hi * K + kk];
            a0[2] = *(const uint32_t*)&W16[(size_t)r_lo * K + kk + 8];
            a0[3] = *(const uint32_t*)&W16[(size_t)r_hi * K + kk + 8];
            a1[0] = *(const uint32_t*)&W16[(size_t)r_lo * K + kk + 16];
            a1[1] = *(const uint32_t*)&W16[(size_t)r_hi * K + kk + 16];
            a1[2] = *(const uint32_t*)&W16[(size_t)r_lo * K + kk + 24];
            a1[3] = *(const uint32_t*)&W16[(size_t)r_hi * K + kk + 24];
        }
        uint32_t bbase = bsm[ks & 1] + lmrow;
#pragma unroll
        for (int j = 0; j < 8; j++) {
            uint32_t b0, b1, b2, b3;
            ldsm4(b0, b1, b2, b3, bbase + (uint32_t)(j * 1152));
            uint32_t bf0[2] = { b0, b1 };
            uint32_t bf1[2] = { b2, b3 };
            mma_f16(acc[j], a0, bf0);
            mma_f16(acc[j], a1, bf1);
        }
        __syncthreads();
    }

    float b_lo = bias[r_lo], b_hi = bias[r_hi];
    if (outh) {
        uint16_t* Ob = outh + (size_t)b * M * N_;
#pragma unroll
        for (int j = 0; j < 8; j++) {
            int n = n0 + j * 8 + 2 * m;
            *(uint32_t*)&Ob[(size_t)r_lo * N_ + n] = f16x2(acc[j][0] + b_lo, acc[j][1] + b_lo);
            *(uint32_t*)&Ob[(size_t)r_hi * N_ + n] = f16x2(acc[j][2] + b_hi, acc[j][3] + b_hi);
        }
    } else {
        float* Ob = outf + (size_t)b * M * N_;
        const float* resb = res + (size_t)b * M * N_;
#pragma unroll
        for (int j = 0; j < 8; j++) {
            int n = n0 + j * 8 + 2 * m;
            size_t olo = (size_t)r_lo * N_ + n;
            size_t ohi = (size_t)r_hi * N_ + n;
            float2 rl = *(const float2*)&resb[olo];
            float2 rh = *(const float2*)&resb[ohi];
            float2 vlo; vlo.x = acc[j][0] + b_lo + rl.x; vlo.y = acc[j][1] + b_lo + rl.y;
            float2 vhi; vhi.x = acc[j][2] + b_hi + rh.x; vhi.y = acc[j][3] + b_hi + rh.y;
            *(float2*)&Ob[olo] = vlo;
            *(float2*)&Ob[ohi] = vhi;
        }
    }
}

// ---------------------------------------------------------------------------
// Repack K: fp16 [d][n] -> key-major fp16 [bh][key][64]
// ---------------------------------------------------------------------------
__global__ void repack_k_k() {
    int bh = blockIdx.y;
    int b = bh >> 2, h = bh & 3;
    const uint16_t* kb = g_qkvh + ((size_t)b * 3 * C_ + C_ + h * HD_) * N_;
    int key0 = blockIdx.x * 64;
    int t = threadIdx.x;

    __shared__ uint16_t kt[64][65];

    int key = t & 63, dg = t >> 6;
#pragma unroll
    for (int i = 0; i < 16; i++) {
        int d = dg * 16 + i;
        kt[d][key] = kb[(size_t)d * N_ + key0 + key];
    }
    __syncthreads();

    int okey = t >> 2, c = t & 3;
    uint32_t pk[8];
#pragma unroll
    for (int u = 0; u < 8; u++) {
        pk[u] = (uint32_t)kt[c * 16 + 2 * u][okey] | ((uint32_t)kt[c * 16 + 2 * u + 1][okey] << 16);
    }
    uint16_t* orow = g_kt + ((size_t)bh * N_ + key0 + okey) * HD_ + c * 16;
    *(uint4*)(orow)     = *(uint4*)&pk[0];
    *(uint4*)(orow + 8) = *(uint4*)&pk[4];
}

// ---------------------------------------------------------------------------
// Flash attention: fp16 MMA, ldmatrix fragment loads, 3-stage cp.async.
// Stage layout (dynamic smem): [3] x { K[64*72 hw], V[64*72 hw] } = 55296 B.
// ---------------------------------------------------------------------------
#define ATT_STG   18432          // bytes per stage (K 9216 + V 9216)
#define ATT_SMEM  (3 * ATT_STG)  // 55296

__device__ __forceinline__ void attn_prefetch(uint32_t base, int stg,
                                              const uint16_t* khb, const uint16_t* vhb,
                                              int k0t, int tid) {
    uint32_t kb = base + (uint32_t)stg * ATT_STG;
    uint32_t vb = kb + 9216;
#pragma unroll
    for (int it = 0; it < 4; it++) {
        int idx = it * 128 + tid;
        int r = idx >> 3, c = idx & 7;
        cpa16(kb + (uint32_t)(r * 144 + c * 16), khb + (size_t)(k0t + r) * HD_ + c * 8);
    }
#pragma unroll
    for (int it = 0; it < 4; it++) {
        int idx = it * 128 + tid;
        int r = idx >> 3, c = idx & 7;
        cpa16(vb + (uint32_t)(r * 144 + c * 16), vhb + (size_t)r * N_ + k0t + c * 8);
    }
    cpa_commit();
}

__global__ __launch_bounds__(128, 4) void attn_k() {
    int qt = blockIdx.x, h = blockIdx.y, b = blockIdx.z;
    int bh = b * NH_ + h;
    const uint16_t* qb  = g_qkvh + ((size_t)b * 3 * C_ + h * HD_) * N_;
    const uint16_t* khb = g_kt + (size_t)bh * N_ * HD_;
    const uint16_t* vhb = g_qkvh + ((size_t)b * 3 * C_ + 2 * C_ + h * HD_) * N_;

    extern __shared__ uint16_t smh[];
    uint32_t base = smem_u32(smh);

    int tid = threadIdx.x, w = tid >> 5, lane = tid & 31;
    int g = lane >> 2, m = lane & 3;
    int q0 = qt * 64;
    uint32_t lmrow = (uint32_t)((lane & 7) * 144 + (lane >> 3) * 16);

    // prologue: tiles 0 and 1
    attn_prefetch(base, 0, khb, vhb, 0, tid);
    attn_prefetch(base, 1, khb, vhb, 64, tid);

    // Q A-fragments (fp16), scaled for log2-domain softmax
    const float qs = SCALE_ * LOG2E_;
    uint32_t Aq[4][4];
    int qlo = q0 + w * 16 + g, qhi = qlo + 8;
#pragma unroll
    for (int t = 0; t < 4; t++) {
        int d0 = t * 16 + 2 * m;
#pragma unroll
        for (int hseg = 0; hseg < 2; hseg++) {
            int d = d0 + hseg * 8;
            float a0 = __half2float(__ushort_as_half(qb[(size_t)d * N_ + qlo])) * qs;
            float a1 = __half2float(__ushort_as_half(qb[(size_t)(d + 1) * N_ + qlo])) * qs;
            float a2 = __half2float(__ushort_as_half(qb[(size_t)d * N_ + qhi])) * qs;
            float a3 = __half2float(__ushort_as_half(qb[(size_t)(d + 1) * N_ + qhi])) * qs;
            Aq[t][2 * hseg]     = f16x2(a0, a1);
            Aq[t][2 * hseg + 1] = f16x2(a2, a3);
        }
    }

    float O[8][4];
#pragma unroll
    for (int j = 0; j < 8; j++)
#pragma unroll
        for (int i = 0; i < 4; i++) O[j][i] = 0.f;
    float mlo = -1e30f, mhi = -1e30f, slo = 0.f, shi = 0.f;

    const int NT = N_ / 64;
    for (int kt = 0; kt < NT; kt++) {
        // issue kt+2 (stage freed by kt-1, protected by previous trailing sync)
        if (kt + 2 < NT) {
            attn_prefetch(base, (kt + 2) % 3, khb, vhb, (kt + 2) * 64, tid);
            cpa_wait2();
        } else if (kt + 1 < NT) {
            cpa_wait1();
        } else {
            cpa_wait0();
        }
        __syncthreads();

        uint32_t kbase = base + (uint32_t)(kt % 3) * ATT_STG + lmrow;
        uint32_t vbase = kbase + 9216;

        // S = Q K^T  (ldmatrix x4: (b0,b1) for t, t+1)
        float S[8][4];
#pragma unroll
        for (int j = 0; j < 8; j++) {
            S[j][0] = S[j][1] = S[j][2] = S[j][3] = 0.f;
            uint32_t k0, k1, k2, k3, k4, k5, k6, k7;
            ldsm4(k0, k1, k2, k3, kbase + (uint32_t)(j * 1152));
            ldsm4(k4, k5, k6, k7, kbase + (uint32_t)(j * 1152 + 64));
            {
                uint32_t bf[2] = { k0, k1 };
                mma_f16(S[j], Aq[0], bf);
            }
            {
                uint32_t bf[2] = { k2, k3 };
                mma_f16(S[j], Aq[1], bf);
            }
            {
                uint32_t bf[2] = { k4, k5 };
                mma_f16(S[j], Aq[2], bf);
            }
            {
                uint32_t bf[2] = { k6, k7 };
                mma_f16(S[j], Aq[3], bf);
            }
        }

        // Online softmax (log2 domain)
        float tlo = -1e30f, thi = -1e30f;
#pragma unroll
        for (int j = 0; j < 8; j++) {
            tlo = fmaxf(tlo, fmaxf(S[j][0], S[j][1]));
            thi = fmaxf(thi, fmaxf(S[j][2], S[j][3]));
        }
#pragma unroll
        for (int o = 1; o <= 2; o <<= 1) {
            tlo = fmaxf(tlo, __shfl_xor_sync(0xffffffffu, tlo, o));
            thi = fmaxf(thi, __shfl_xor_sync(0xffffffffu, thi, o));
        }
        float nlo = fmaxf(mlo, tlo), nhi = fmaxf(mhi, thi);
        float clo = ex2f(mlo - nlo), chi = ex2f(mhi - nhi);
        mlo = nlo; mhi = nhi;
        float ssl = 0.f, ssh = 0.f;
        uint32_t Pf[8][2];
#pragma unroll
        for (int j = 0; j < 8; j++) {
            float p0 = ex2f(S[j][0] - nlo);
            float p1 = ex2f(S[j][1] - nlo);
            float p2 = ex2f(S[j][2] - nhi);
            float p3 = ex2f(S[j][3] - nhi);
            ssl += p0 + p1; ssh += p2 + p3;
            O[j][0] *= clo; O[j][1] *= clo; O[j][2] *= chi; O[j][3] *= chi;
            Pf[j][0] = f16x2(p0, p1);
            Pf[j][1] = f16x2(p2, p3);
        }
#pragma unroll
        for (int o = 1; o <= 2; o <<= 1) {
            ssl += __shfl_xor_sync(0xffffffffu, ssl, o);
            ssh += __shfl_xor_sync(0xffffffffu, ssh, o);
        }
        slo = slo * clo + ssl;
        shi = shi * chi + ssh;

        // O += P @ V  (register-relay P; ldmatrix V fragments)
#pragma unroll
        for (int j = 0; j < 8; j++) {
            uint32_t v0, v1, v2, v3, v4, v5, v6, v7;
            ldsm4(v0, v1, v2, v3, vbase + (uint32_t)(j * 1152));
            ldsm4(v4, v5, v6, v7, vbase + (uint32_t)(j * 1152 + 64));
            {
                uint32_t bf[2] = { v0, v1 };
                mma_f16(O[j], &Pf[0][0], bf);
            }
            {
                uint32_t bf[2] = { v2, v3 };
                mma_f16(O[j], &Pf[2][0], bf);
            }
            {
                uint32_t bf[2] = { v4, v5 };
                mma_f16(O[j], &Pf[4][0], bf);
            }
            {
                uint32_t bf[2] = { v6, v7 };
                mma_f16(O[j], &Pf[6][0], bf);
            }
        }
        __syncthreads();   // all stage reads done before it is refilled
    }

    // Epilogue: normalize, write fp16 ao_t[b][q][c]
    uint16_t* aob = g_aot + ((size_t)b * N_) * C_ + h * HD_;
    float ilo = 1.f / slo, ihi = 1.f / shi;
#pragma unroll
    for (int j = 0; j < 8; j++) {
        int d = j * 8 + 2 * m;
        *(uint32_t*)&aob[(size_t)qlo * C_ + d] = f16x2(O[j][0] * ilo, O[j][1] * ilo);
        *(uint32_t*)&aob[(size_t)qhi * C_ + d] = f16x2(O[j][2] * ihi, O[j][3] * ihi);
    }
}

// ---------------------------------------------------------------------------
// Launch sequence
// ---------------------------------------------------------------------------
extern "C" void kernel_launch(void* const* d_in, const int* in_sizes, int n_in,
                              void* d_out, int out_size) {
    const float* x    = (const float*)d_in[0];
    const float* gw   = (const float*)d_in[1];
    const float* gb   = (const float*)d_in[2];
    const float* qkvw = (const float*)d_in[3];
    const float* qkvb = (const float*)d_in[4];
    const float* pw   = (const float*)d_in[5];
    const float* pb   = (const float*)d_in[6];
    float* out = (float*)d_out;

    uint16_t *hnt, *qkvh, *aot, *w16;
    cudaGetSymbolAddress((void**)&hnt,  g_hnt);
    cudaGetSymbolAddress((void**)&qkvh, g_qkvh);
    cudaGetSymbolAddress((void**)&aot,  g_aot);
    cudaGetSymbolAddress((void**)&w16,  g_w16);

    // 1) GroupNorm stats (two-phase)
    gn_stats1_k<<<256, 256>>>(x);
    gn_stats2_k<<<1, 32>>>();
    // 2) Weight packs
    w2h_k<<<(3 * C_ * C_ / 4 + 255) / 256, 256>>>(qkvw, 3 * C_ * C_ / 4, 0);
    w2h_k<<<(C_ * C_ / 4 + 255) / 256, 256>>>(pw, C_ * C_ / 4, 3 * C_ * C_);
    // 3) GN apply + transpose -> hnt fp16 [b][n][c]
    {
        dim3 g(N_ / 64, C_ / 64, B_);
        gn_t_k<<<g, 256>>>(x, gw, gb);
    }
    // 4) QKV fp16 GEMM -> qkvh fp16 [b][3C][n]
    {
        dim3 g(N_ / 64, (3 * C_) / 64, B_);
        hgemm_k<<<g, 128>>>(w16, hnt, qkvb, nullptr, qkvh, nullptr, 3 * C_);
    }
    // 5) K transpose
    {
        dim3 g(N_ / 64, B_ * NH_);
        repack_k_k<<<g, 256>>>();
    }
    // 6) Flash attention -> aot fp16 [b][n][c]
    cudaFuncSetAttribute(attn_k, cudaFuncAttributeMaxDynamicSharedMemorySize, ATT_SMEM);
    {
        dim3 g(N_ / 64, NH_, B_);
        attn_k<<<g, 128, ATT_SMEM>>>();
    }
    // 7) proj fp16 GEMM + bias + residual -> d_out fp32
    {
        dim3 g(N_ / 64, C_ / 64, B_);
        hgemm_k<<<g, 128>>>(w16 + 3 * C_ * C_, aot, pb, x, nullptr, out, C_);
    }
}